// round 2
// baseline (speedup 1.0000x reference)
#include <cuda_runtime.h>
#include <math.h>

#define D 128
#define MAXN 50000

static const long SZ = (long)MAXN * D;   // 6,400,000 floats per feature buffer

// Scratch layout (single __device__ symbol, offsets in floats):
//  0..5  : Axn, Ahn, Axu, Ahu, Acn, Acu   (aggregation accumulators)
//  6..11 : Zn, Zu, CXn, CXu, HRn, HRu
//  then  : Wzr_n(512*256), Wzr_u(512*256), Wcx_n(256*128), Wcx_u, Wch_n, Wch_u
//  then  : bzr_n(256), bzr_u(256), bcx_n(128), bcx_u(128), bch_n(128), bch_u(128)
__device__ float g_buf[12L * 50000L * 128L + 2 * (512 * 256) + 4 * (256 * 128) + 2 * 256 + 4 * 128];
__device__ int g_deg[2 * MAXN];

// ---------------------------------------------------------------------------
// zero scratch accumulators + degree counters
__global__ void zero_kernel(float4* p, long n4, int* d, int nd) {
    long stride = (long)gridDim.x * blockDim.x;
    long i0 = blockIdx.x * (long)blockDim.x + threadIdx.x;
    for (long j = i0; j < n4; j += stride) p[j] = make_float4(0.f, 0.f, 0.f, 0.f);
    for (long j = i0; j < nd; j += stride) d[j] = 0;
}

// ---------------------------------------------------------------------------
__global__ void count_deg(const int* __restrict__ dst, int E, int* __restrict__ deg) {
    int i = blockIdx.x * blockDim.x + threadIdx.x;
    if (i < E) atomicAdd(&deg[dst[i]], 1);
}

// warp-per-edge: scatter-add two feature rows (x and h) of the source node
__global__ void agg2_kernel(const float* __restrict__ fx, const float* __restrict__ fh,
                            const int* __restrict__ src, const int* __restrict__ dst, int E,
                            float* __restrict__ Ax, float* __restrict__ Ah) {
    long gid = blockIdx.x * (long)blockDim.x + threadIdx.x;
    int e = (int)(gid >> 5);
    int lane = (int)(gid & 31);
    if (e >= E) return;
    int s = src[e], d = dst[e];
    float4 vx = *(const float4*)(fx + (long)s * D + lane * 4);
    float4 vh = *(const float4*)(fh + (long)s * D + lane * 4);
#if __CUDA_ARCH__ >= 900
    atomicAdd((float4*)(Ax + (long)d * D + lane * 4), vx);
    atomicAdd((float4*)(Ah + (long)d * D + lane * 4), vh);
#else
    float* ax = Ax + (long)d * D + lane * 4;
    float* ah = Ah + (long)d * D + lane * 4;
    atomicAdd(ax + 0, vx.x); atomicAdd(ax + 1, vx.y); atomicAdd(ax + 2, vx.z); atomicAdd(ax + 3, vx.w);
    atomicAdd(ah + 0, vh.x); atomicAdd(ah + 1, vh.y); atomicAdd(ah + 2, vh.z); atomicAdd(ah + 3, vh.w);
#endif
}

__global__ void agg1_kernel(const float* __restrict__ f,
                            const int* __restrict__ src, const int* __restrict__ dst, int E,
                            float* __restrict__ A) {
    long gid = blockIdx.x * (long)blockDim.x + threadIdx.x;
    int e = (int)(gid >> 5);
    int lane = (int)(gid & 31);
    if (e >= E) return;
    int s = src[e], d = dst[e];
    float4 v = *(const float4*)(f + (long)s * D + lane * 4);
#if __CUDA_ARCH__ >= 900
    atomicAdd((float4*)(A + (long)d * D + lane * 4), v);
#else
    float* a = A + (long)d * D + lane * 4;
    atomicAdd(a + 0, v.x); atomicAdd(a + 1, v.y); atomicAdd(a + 2, v.z); atomicAdd(a + 3, v.w);
#endif
}

// divide accumulated sums by max(deg,1) — two buffers at once
__global__ void norm2_kernel(float* __restrict__ A, float* __restrict__ B,
                             const int* __restrict__ deg, int n) {
    int i = blockIdx.x * blockDim.x + threadIdx.x;   // one float4 per thread
    int total = n * (D / 4);
    if (i >= total) return;
    int node = i >> 5;
    float inv = 1.f / (float)max(deg[node], 1);
    float4* a = (float4*)A + i;
    float4 va = *a; va.x *= inv; va.y *= inv; va.z *= inv; va.w *= inv; *a = va;
    float4* b = (float4*)B + i;
    float4 vb = *b; vb.x *= inv; vb.y *= inv; vb.z *= inv; vb.w *= inv; *b = vb;
}

__global__ void norm1_kernel(float* __restrict__ A, const int* __restrict__ deg, int n) {
    int i = blockIdx.x * blockDim.x + threadIdx.x;
    int total = n * (D / 4);
    if (i >= total) return;
    int node = i >> 5;
    float inv = 1.f / (float)max(deg[node], 1);
    float4* a = (float4*)A + i;
    float4 va = *a; va.x *= inv; va.y *= inv; va.z *= inv; va.w *= inv; *a = va;
}

// ---------------------------------------------------------------------------
// weight stacking
// Wzr [512,256]: rows: [Wl[gz..],[Wr[gz]],[Wl[gz+1]],[Wr[gz+1]]; cols<128 -> gz=0 (z), else gz=2 (r)
__global__ void build_wzr(const float* __restrict__ Wl, const float* __restrict__ Wr,
                          float* __restrict__ out, int t) {
    int j = blockIdx.x * blockDim.x + threadIdx.x;
    if (j >= 512 * 256) return;
    int k = j >> 8;
    int c = j & 255;
    int gz = (c < 128) ? 0 : 2;
    int cc = c & 127;
    int part = k >> 7;
    int kk = k & 127;
    int g = gz + (part >> 1);
    const float* src = (part & 1) ? Wr : Wl;
    out[j] = src[(((long)(g * 2 + t)) * 128 + kk) * 128 + cc];
}

// W2 [256,128]: rows [Wl[g]; Wr[g]]
__global__ void build_w2(const float* __restrict__ Wl, const float* __restrict__ Wr,
                         float* __restrict__ out, int g, int t) {
    int j = blockIdx.x * blockDim.x + threadIdx.x;
    if (j >= 256 * 128) return;
    int k = j >> 7;
    int c = j & 127;
    int part = k >> 7;
    int kk = k & 127;
    const float* src = part ? Wr : Wl;
    out[j] = src[(((long)(g * 2 + t)) * 128 + kk) * 128 + c];
}

__global__ void build_bias(const float* __restrict__ b,
                           float* bzr_n, float* bzr_u, float* bcx_n, float* bcx_u,
                           float* bch_n, float* bch_u) {
    int c = threadIdx.x;
    if (c >= 128) return;
#define BB(g, t) b[((g) * 2 + (t)) * 128 + c]
    bzr_n[c]       = BB(0, 0) + BB(1, 0);
    bzr_n[128 + c] = BB(2, 0) + BB(3, 0);
    bzr_u[c]       = BB(0, 1) + BB(1, 1);
    bzr_u[128 + c] = BB(2, 1) + BB(3, 1);
    bcx_n[c] = BB(4, 0);
    bcx_u[c] = BB(4, 1);
    bch_n[c] = BB(5, 0);
    bch_u[c] = BB(5, 1);
#undef BB
}

// ---------------------------------------------------------------------------
// fused GEMM: C = [A0|A1|A2|A3] @ W + bias, with epilogue modes:
//   mode 0 (ZR): cols<128 -> Z=sigmoid(v); cols>=128 -> HR = sigmoid(v) * H
//   mode 1 (CX): store v
//   mode 2 (CH): ht=tanh(v+CX); out = Z*H + (1-Z)*ht
#define BM 128
#define BN 128
#define BK 16
#define TM 8
#define TN 8

__device__ __forceinline__ float sigmoidf_(float x) { return 1.f / (1.f + expf(-x)); }

__global__ void __launch_bounds__(256, 2) gemm_kernel(
    const float* __restrict__ A0, const float* __restrict__ A1,
    const float* __restrict__ A2, const float* __restrict__ A3,
    const float* __restrict__ W, const float* __restrict__ bias,
    int M, int N, int nparts, int mode,
    const float* __restrict__ H, const float* __restrict__ Z, const float* __restrict__ CX,
    float* __restrict__ out0, float* __restrict__ out1) {
    __shared__ float As[BK][BM];
    __shared__ float Ws[BK][BN];
    int tid = threadIdx.x;
    int row0 = blockIdx.y * BM;
    int col0 = blockIdx.x * BN;

    float acc[TM][TN];
#pragma unroll
    for (int i = 0; i < TM; i++)
#pragma unroll
        for (int j = 0; j < TN; j++) acc[i][j] = 0.f;

    int tr = (tid >> 4) * TM;
    int tc = (tid & 15) * TN;
    int K = nparts * D;

    for (int k0 = 0; k0 < K; k0 += BK) {
        const float* Ap = (k0 < D) ? A0 : (k0 < 2 * D) ? A1 : (k0 < 3 * D) ? A2 : A3;
        int kk0 = k0 & (D - 1);
#pragma unroll
        for (int i = 0; i < 2; i++) {
            int idx = tid + i * 256;      // 0..511
            int r = idx >> 2;             // 0..127
            int kq = (idx & 3) * 4;       // 0,4,8,12
            int grow = row0 + r;
            float4 v = make_float4(0.f, 0.f, 0.f, 0.f);
            if (grow < M) v = *(const float4*)(Ap + (long)grow * D + kk0 + kq);
            As[kq + 0][r] = v.x; As[kq + 1][r] = v.y; As[kq + 2][r] = v.z; As[kq + 3][r] = v.w;
        }
#pragma unroll
        for (int i = 0; i < 2; i++) {
            int idx = tid + i * 256;
            int kr = idx >> 5;            // 0..15
            int cq = (idx & 31) * 4;      // 0..124
            *(float4*)&Ws[kr][cq] = *(const float4*)(W + (long)(k0 + kr) * N + col0 + cq);
        }
        __syncthreads();
#pragma unroll
        for (int kk = 0; kk < BK; kk++) {
            float a[TM], bfr[TN];
            *(float4*)&a[0]   = *(const float4*)&As[kk][tr];
            *(float4*)&a[4]   = *(const float4*)&As[kk][tr + 4];
            *(float4*)&bfr[0] = *(const float4*)&Ws[kk][tc];
            *(float4*)&bfr[4] = *(const float4*)&Ws[kk][tc + 4];
#pragma unroll
            for (int i = 0; i < TM; i++)
#pragma unroll
                for (int j = 0; j < TN; j++)
                    acc[i][j] = fmaf(a[i], bfr[j], acc[i][j]);
        }
        __syncthreads();
    }

#pragma unroll
    for (int i = 0; i < TM; i++) {
        int r = row0 + tr + i;
        if (r >= M) break;
        long rbase = (long)r * D;
#pragma unroll
        for (int j = 0; j < TN; j++) {
            int c = col0 + tc + j;
            float v = acc[i][j] + bias[c];
            if (mode == 0) {
                if (c < D) {
                    out0[rbase + c] = sigmoidf_(v);
                } else {
                    int cc = c - D;
                    float rr = sigmoidf_(v);
                    out1[rbase + cc] = rr * H[rbase + cc];
                }
            } else if (mode == 1) {
                out0[rbase + c] = v;
            } else {
                float ht = tanhf(v + CX[rbase + c]);
                float z = Z[rbase + c];
                out0[rbase + c] = z * H[rbase + c] + (1.f - z) * ht;
            }
        }
    }
}

// ---------------------------------------------------------------------------
extern "C" void kernel_launch(void* const* d_in, const int* in_sizes, int n_in,
                              void* d_out, int out_size) {
    const float* x_user = (const float*)d_in[0];
    const float* x_news = (const float*)d_in[1];
    const float* h_user = (const float*)d_in[2];
    const float* h_news = (const float*)d_in[3];
    const float* Wl     = (const float*)d_in[4];
    const float* Wr     = (const float*)d_in[5];
    const float* bb     = (const float*)d_in[6];
    const int* src_un   = (const int*)d_in[7];
    const int* dst_un   = (const int*)d_in[8];
    const int* src_nu   = (const int*)d_in[9];
    const int* dst_nu   = (const int*)d_in[10];

    int NU = in_sizes[0] / D;
    int NN = in_sizes[1] / D;
    int E1 = in_sizes[7];
    int E2 = in_sizes[9];

    float* base = nullptr;
    int* deg = nullptr;
    cudaGetSymbolAddress((void**)&base, g_buf);
    cudaGetSymbolAddress((void**)&deg, g_deg);

    float* Axn = base + 0 * SZ;
    float* Ahn = base + 1 * SZ;
    float* Axu = base + 2 * SZ;
    float* Ahu = base + 3 * SZ;
    float* Acn = base + 4 * SZ;
    float* Acu = base + 5 * SZ;
    float* Zn  = base + 6 * SZ;
    float* Zu  = base + 7 * SZ;
    float* CXn = base + 8 * SZ;
    float* CXu = base + 9 * SZ;
    float* HRn = base + 10 * SZ;
    float* HRu = base + 11 * SZ;
    float* wp    = base + 12 * SZ;
    float* Wzr_n = wp;               wp += 512 * 256;
    float* Wzr_u = wp;               wp += 512 * 256;
    float* Wcx_n = wp;               wp += 256 * 128;
    float* Wcx_u = wp;               wp += 256 * 128;
    float* Wch_n = wp;               wp += 256 * 128;
    float* Wch_u = wp;               wp += 256 * 128;
    float* bzr_n = wp;               wp += 256;
    float* bzr_u = wp;               wp += 256;
    float* bcx_n = wp;               wp += 128;
    float* bcx_u = wp;               wp += 128;
    float* bch_n = wp;               wp += 128;
    float* bch_u = wp;               wp += 128;

    int* deg_n = deg;
    int* deg_u = deg + MAXN;

    float* out_u = (float*)d_out;                 // h_user' first
    float* out_n = (float*)d_out + (long)NU * D;  // then h_news'

    // 1) zero accumulators + degrees
    zero_kernel<<<4096, 256>>>((float4*)base, (6 * SZ) / 4, deg, NU + NN);

    // 2) stack weights & biases
    build_wzr<<<(512 * 256 + 255) / 256, 256>>>(Wl, Wr, Wzr_n, 0);
    build_wzr<<<(512 * 256 + 255) / 256, 256>>>(Wl, Wr, Wzr_u, 1);
    build_w2<<<(256 * 128 + 255) / 256, 256>>>(Wl, Wr, Wcx_n, 4, 0);
    build_w2<<<(256 * 128 + 255) / 256, 256>>>(Wl, Wr, Wcx_u, 4, 1);
    build_w2<<<(256 * 128 + 255) / 256, 256>>>(Wl, Wr, Wch_n, 5, 0);
    build_w2<<<(256 * 128 + 255) / 256, 256>>>(Wl, Wr, Wch_u, 5, 1);
    build_bias<<<1, 128>>>(bb, bzr_n, bzr_u, bcx_n, bcx_u, bch_n, bch_u);

    // 3) degrees
    count_deg<<<(E1 + 255) / 256, 256>>>(dst_un, E1, deg_n);
    count_deg<<<(E2 + 255) / 256, 256>>>(dst_nu, E2, deg_u);

    // 4) aggregate x and h features (fused per edge direction)
    long thr1 = (long)E1 * 32, thr2 = (long)E2 * 32;
    agg2_kernel<<<(int)((thr1 + 255) / 256), 256>>>(x_user, h_user, src_un, dst_un, E1, Axn, Ahn);
    agg2_kernel<<<(int)((thr2 + 255) / 256), 256>>>(x_news, h_news, src_nu, dst_nu, E2, Axu, Ahu);
    norm2_kernel<<<(NN * 32 + 255) / 256, 256>>>(Axn, Ahn, deg_n, NN);
    norm2_kernel<<<(NU * 32 + 255) / 256, 256>>>(Axu, Ahu, deg_u, NU);

    // 5) z/r gates (K=512, N=256) with fused sigmoid + h*r epilogue
    dim3 gzr(2, (unsigned)((MAXN + BM - 1) / BM));
    dim3 g1(1, (unsigned)((MAXN + BM - 1) / BM));
    gemm_kernel<<<gzr, 256>>>(Axn, x_news, Ahn, h_news, Wzr_n, bzr_n, NN, 256, 4, 0,
                              h_news, nullptr, nullptr, Zn, HRn);
    gemm_kernel<<<gzr, 256>>>(Axu, x_user, Ahu, h_user, Wzr_u, bzr_u, NU, 256, 4, 0,
                              h_user, nullptr, nullptr, Zu, HRu);

    // 6) cx (K=256, N=128)
    gemm_kernel<<<g1, 256>>>(Axn, x_news, nullptr, nullptr, Wcx_n, bcx_n, NN, 128, 2, 1,
                             nullptr, nullptr, nullptr, CXn, nullptr);
    gemm_kernel<<<g1, 256>>>(Axu, x_user, nullptr, nullptr, Wcx_u, bcx_u, NU, 128, 2, 1,
                             nullptr, nullptr, nullptr, CXu, nullptr);

    // 7) aggregate h*r
    agg1_kernel<<<(int)((thr1 + 255) / 256), 256>>>(HRu, src_un, dst_un, E1, Acn);
    agg1_kernel<<<(int)((thr2 + 255) / 256), 256>>>(HRn, src_nu, dst_nu, E2, Acu);
    norm1_kernel<<<(NN * 32 + 255) / 256, 256>>>(Acn, deg_n, NN);
    norm1_kernel<<<(NU * 32 + 255) / 256, 256>>>(Acu, deg_u, NU);

    // 8) ch GEMM with fused tanh + GRU-update epilogue, writing final output
    gemm_kernel<<<g1, 256>>>(Acu, HRu, nullptr, nullptr, Wch_u, bch_u, NU, 128, 2, 2,
                             h_user, Zu, CXu, out_u, nullptr);
    gemm_kernel<<<g1, 256>>>(Acn, HRn, nullptr, nullptr, Wch_n, bch_n, NN, 128, 2, 2,
                             h_news, Zn, CXn, out_n, nullptr);
}

// round 4
// speedup vs baseline: 1.6581x; 1.6581x over previous
#include <cuda_runtime.h>
#include <cuda_bf16.h>
#include <math.h>
#include <stdint.h>

#define D 128
#define MAXN 50000
#define SZF (50000L * 128L)

// fp32: Axn Ahn Axu Ahu Acn Acu Zn Zu CXn CXu (10*SZF)
// packed bf16 hi/lo regions: 12*SZF ; weights+bias tail
__device__ float g_buf[22L * SZF + 2 * 131072 + 4 * 32768 + 1024];
__device__ int g_deg[2 * MAXN];

// ---------------- helpers ----------------
__device__ __forceinline__ uint32_t s2u(const void* p) {
    uint32_t a;
    asm("{ .reg .u64 t; cvta.to.shared.u64 t, %1; cvt.u32.u64 %0, t; }" : "=r"(a) : "l"(p));
    return a;
}
__device__ __host__ __forceinline__ uint32_t SWZ(uint32_t x) { return x ^ ((x >> 3) & 0x70); }

__device__ __forceinline__ float sigf(float x) { return 1.f / (1.f + expf(-x)); }

__device__ __forceinline__ void split4(float4 v, uint2& hu, uint2& lu) {
    __nv_bfloat162 h01 = __floats2bfloat162_rn(v.x, v.y);
    __nv_bfloat162 h23 = __floats2bfloat162_rn(v.z, v.w);
    float lx = v.x - __bfloat162float(__low2bfloat16(h01));
    float ly = v.y - __bfloat162float(__high2bfloat16(h01));
    float lz = v.z - __bfloat162float(__low2bfloat16(h23));
    float lw = v.w - __bfloat162float(__high2bfloat16(h23));
    __nv_bfloat162 l01 = __floats2bfloat162_rn(lx, ly);
    __nv_bfloat162 l23 = __floats2bfloat162_rn(lz, lw);
    hu.x = *reinterpret_cast<uint32_t*>(&h01);
    hu.y = *reinterpret_cast<uint32_t*>(&h23);
    lu.x = *reinterpret_cast<uint32_t*>(&l01);
    lu.y = *reinterpret_cast<uint32_t*>(&l23);
}

__device__ __forceinline__ void split2(float x, float y, uint32_t& hw, uint32_t& lw) {
    __nv_bfloat162 h = __floats2bfloat162_rn(x, y);
    float rx = x - __bfloat162float(__low2bfloat16(h));
    float ry = y - __bfloat162float(__high2bfloat16(h));
    __nv_bfloat162 l = __floats2bfloat162_rn(rx, ry);
    hw = *reinterpret_cast<uint32_t*>(&h);
    lw = *reinterpret_cast<uint32_t*>(&l);
}

// ---------------- simple kernels ----------------
__global__ void zero_kernel(float4* p, long n4, int* d, int nd) {
    long stride = (long)gridDim.x * blockDim.x;
    long i0 = blockIdx.x * (long)blockDim.x + threadIdx.x;
    for (long j = i0; j < n4; j += stride) p[j] = make_float4(0.f, 0.f, 0.f, 0.f);
    for (long j = i0; j < nd; j += stride) d[j] = 0;
}

__global__ void count_deg(const int* __restrict__ dst, int E, int* __restrict__ deg) {
    int i = blockIdx.x * blockDim.x + threadIdx.x;
    if (i < E) atomicAdd(&deg[dst[i]], 1);
}

__global__ void agg2_kernel(const float* __restrict__ fx, const float* __restrict__ fh,
                            const int* __restrict__ src, const int* __restrict__ dst, int E,
                            float* __restrict__ Ax, float* __restrict__ Ah) {
    long gid = blockIdx.x * (long)blockDim.x + threadIdx.x;
    int e = (int)(gid >> 5);
    int lane = (int)(gid & 31);
    if (e >= E) return;
    int s = src[e], d = dst[e];
    float4 vx = *(const float4*)(fx + (long)s * D + lane * 4);
    float4 vh = *(const float4*)(fh + (long)s * D + lane * 4);
    atomicAdd((float4*)(Ax + (long)d * D + lane * 4), vx);
    atomicAdd((float4*)(Ah + (long)d * D + lane * 4), vh);
}

// gather packed hi/lo bf16 rows (reconstruct fp32), scatter-add
__global__ void agg1_packed(const char* __restrict__ P, long Mb,
                            const int* __restrict__ src, const int* __restrict__ dst, int E,
                            float* __restrict__ A) {
    long gid = blockIdx.x * (long)blockDim.x + threadIdx.x;
    int e = (int)(gid >> 5);
    int lane = (int)(gid & 31);
    if (e >= E) return;
    int s = src[e], d = dst[e];
    int c4 = lane * 4;
    int q = c4 >> 6;
    int inner = c4 & 63;
    uint32_t sw = SWZ((uint32_t)s * 128u + (uint32_t)inner * 2u);
    uint2 hu = *(const uint2*)(P + (long)q * Mb + sw);
    uint2 lu = *(const uint2*)(P + 2 * Mb + (long)q * Mb + sw);
    float2 a = __bfloat1622float2(*reinterpret_cast<__nv_bfloat162*>(&hu.x));
    float2 b = __bfloat1622float2(*reinterpret_cast<__nv_bfloat162*>(&hu.y));
    float2 c = __bfloat1622float2(*reinterpret_cast<__nv_bfloat162*>(&lu.x));
    float2 dd = __bfloat1622float2(*reinterpret_cast<__nv_bfloat162*>(&lu.y));
    float4 v = make_float4(a.x + c.x, a.y + c.y, b.x + dd.x, b.y + dd.y);
    atomicAdd((float4*)(A + (long)d * D + c4), v);
}

// fp32 [M,128] (* 1/deg optional) -> packed hi/lo bf16 SW128 chunks
__global__ void pack_kernel(const float* __restrict__ src, const int* __restrict__ deg,
                            int M, char* __restrict__ dst) {
    long i = blockIdx.x * (long)blockDim.x + threadIdx.x;
    if (i >= (long)M * 32) return;
    int row = (int)(i >> 5);
    int c4 = ((int)i & 31) * 4;
    float inv = 1.f;
    if (deg) inv = 1.f / (float)max(deg[row], 1);
    float4 v = ((const float4*)src)[i];
    v.x *= inv; v.y *= inv; v.z *= inv; v.w *= inv;
    uint2 hu, lu;
    split4(v, hu, lu);
    int q = c4 >> 6;
    int inner = c4 & 63;
    uint32_t sw = SWZ((uint32_t)row * 128u + (uint32_t)inner * 2u);
    long Mb = (long)M * 128;
    *(uint2*)(dst + (long)q * Mb + sw) = hu;
    *(uint2*)(dst + 2 * Mb + (long)q * Mb + sw) = lu;
}

// ---------------- weight packing ----------------
// zr: parts [Wl[gz],Wr[gz],Wl[gz+1],Wr[gz+1]], gz=(n<128)?0:2. B[n][k] layout,
// blocks ((p*2+sec)*2+q), each N rows x 128B, SW128.
__global__ void pack_w_zr(const float* __restrict__ Wl, const float* __restrict__ Wr,
                          char* __restrict__ dst, int t) {
    int j = blockIdx.x * blockDim.x + threadIdx.x;
    if (j >= 4 * 256 * 128) return;
    int k = j & 127;
    int n = (j >> 7) & 255;
    int p = j >> 15;
    int gz = (n < 128) ? 0 : 2;
    int cc = n & 127;
    int g = gz + (p >> 1);
    const float* S = (p & 1) ? Wr : Wl;
    float w = S[((long)(g * 2 + t) * 128 + k) * 128 + cc];
    __nv_bfloat16 h = __float2bfloat16_rn(w);
    float lof = w - __bfloat162float(h);
    __nv_bfloat16 l = __float2bfloat16_rn(lof);
    int q = k >> 6;
    int inner = k & 63;
    uint32_t sw = SWZ((uint32_t)n * 128u + (uint32_t)inner * 2u);
    const int Nb = 256 * 128;
    *(unsigned short*)(dst + (size_t)((p * 2 + 0) * 2 + q) * Nb + sw) = *reinterpret_cast<unsigned short*>(&h);
    *(unsigned short*)(dst + (size_t)((p * 2 + 1) * 2 + q) * Nb + sw) = *reinterpret_cast<unsigned short*>(&l);
}

__global__ void pack_w2(const float* __restrict__ Wl, const float* __restrict__ Wr,
                        char* __restrict__ dst, int g, int t) {
    int j = blockIdx.x * blockDim.x + threadIdx.x;
    if (j >= 2 * 128 * 128) return;
    int k = j & 127;
    int n = (j >> 7) & 127;
    int p = j >> 14;
    const float* S = p ? Wr : Wl;
    float w = S[((long)(g * 2 + t) * 128 + k) * 128 + n];
    __nv_bfloat16 h = __float2bfloat16_rn(w);
    float lof = w - __bfloat162float(h);
    __nv_bfloat16 l = __float2bfloat16_rn(lof);
    int q = k >> 6;
    int inner = k & 63;
    uint32_t sw = SWZ((uint32_t)n * 128u + (uint32_t)inner * 2u);
    const int Nb = 128 * 128;
    *(unsigned short*)(dst + (size_t)((p * 2 + 0) * 2 + q) * Nb + sw) = *reinterpret_cast<unsigned short*>(&h);
    *(unsigned short*)(dst + (size_t)((p * 2 + 1) * 2 + q) * Nb + sw) = *reinterpret_cast<unsigned short*>(&l);
}

__global__ void build_bias(const float* __restrict__ b,
                           float* bzr_n, float* bzr_u, float* bcx_n, float* bcx_u,
                           float* bch_n, float* bch_u) {
    int c = threadIdx.x;
    if (c >= 128) return;
#define BB(g, t) b[((g) * 2 + (t)) * 128 + c]
    bzr_n[c]       = BB(0, 0) + BB(1, 0);
    bzr_n[128 + c] = BB(2, 0) + BB(3, 0);
    bzr_u[c]       = BB(0, 1) + BB(1, 1);
    bzr_u[128 + c] = BB(2, 1) + BB(3, 1);
    bcx_n[c] = BB(4, 0);
    bcx_u[c] = BB(4, 1);
    bch_n[c] = BB(5, 0);
    bch_u[c] = BB(5, 1);
#undef BB
}

// ---------------- HMMA GEMM (baseline PTX: mma.sync + ldmatrix + cp.async) ----
struct GP {
    const char* hi[4];
    const char* lo[4];
    const char* B;
    const float* bias;
    const float* H;
    const float* Z;
    const float* CX;
    float* out0;
    char* outHR;
    long Mb;          // M*128 bytes per packed chunk
    int M, N, nparts, mode;   // mode 0=zr, 1=cx, 2=ch
};

__device__ __forceinline__ void epi_pair(const GP& g, int row, int c, float v0, float v1) {
    v0 += g.bias[c];
    v1 += g.bias[c + 1];
    long rb = (long)row * D;
    if (g.mode == 0) {
        if (c < 128) {
            g.out0[rb + c] = sigf(v0);
            g.out0[rb + c + 1] = sigf(v1);
        } else {
            int cc = c - 128;
            float r0 = sigf(v0) * g.H[rb + cc];
            float r1 = sigf(v1) * g.H[rb + cc + 1];
            uint32_t hw, lw;
            split2(r0, r1, hw, lw);
            uint32_t sw = SWZ((uint32_t)row * 128u + (uint32_t)(cc & 63) * 2u);
            int q = cc >> 6;
            *(uint32_t*)(g.outHR + (long)q * g.Mb + sw) = hw;
            *(uint32_t*)(g.outHR + 2 * g.Mb + (long)q * g.Mb + sw) = lw;
        }
    } else if (g.mode == 1) {
        g.out0[rb + c] = v0;
        g.out0[rb + c + 1] = v1;
    } else {
        float z0 = g.Z[rb + c], z1 = g.Z[rb + c + 1];
        float h0 = g.H[rb + c], h1 = g.H[rb + c + 1];
        float t0 = tanhf(v0 + g.CX[rb + c]);
        float t1 = tanhf(v1 + g.CX[rb + c + 1]);
        g.out0[rb + c] = z0 * h0 + (1.f - z0) * t0;
        g.out0[rb + c + 1] = z1 * h1 + (1.f - z1) * t1;
    }
}

__global__ void __launch_bounds__(256) gemm_mma(GP g) {
    extern __shared__ char smem[];
    uint32_t sb = s2u(smem);
    int tid = threadIdx.x;
    int lane = tid & 31, wid = tid >> 5;
    int wm = wid & 3, wn = wid >> 2;          // 4x2 warp grid
    int row0 = blockIdx.x * 128;
    int col0 = blockIdx.y * 128;
    long Nb = (long)g.N * 128;
    int C = g.nparts * 6;                      // stages: parts x 3 terms x 2 chunks

    float acc[2][8][4];
#pragma unroll
    for (int i = 0; i < 2; i++)
#pragma unroll
        for (int j = 0; j < 8; j++)
#pragma unroll
            for (int k = 0; k < 4; k++) acc[i][j][k] = 0.f;

    auto issue = [&](int t) {
        int buf = t & 1;
        int p = t / 6, r = t % 6, sec = r >> 1, q = r & 1;
        const char* Asrc = ((sec == 1) ? g.lo[p] : g.hi[p]) + (long)q * g.Mb + (long)row0 * 128;
        const char* Bsrc = g.B + (size_t)((p * 2 + (sec == 2 ? 1 : 0)) * 2 + q) * Nb
                         + (long)col0 * 128;
        uint32_t Ad = sb + (uint32_t)buf * 32768u;
        uint32_t Bd = Ad + 16384u;
#pragma unroll
        for (int j = 0; j < 4; j++) {
            int idx = tid + j * 256;
            uint32_t sz = (row0 + (idx >> 3) < g.M) ? 16u : 0u;
            asm volatile("cp.async.cg.shared.global [%0], [%1], 16, %2;"
                         :: "r"(Ad + idx * 16), "l"(Asrc + (long)idx * 16), "r"(sz));
        }
#pragma unroll
        for (int j = 0; j < 4; j++) {
            int idx = tid + j * 256;
            asm volatile("cp.async.cg.shared.global [%0], [%1], 16;"
                         :: "r"(Bd + idx * 16), "l"(Bsrc + (long)idx * 16));
        }
        asm volatile("cp.async.commit_group;" ::: "memory");
    };

    issue(0);
    issue(1);

    for (int t = 0; t < C; t++) {
        if (t == C - 1) asm volatile("cp.async.wait_group 0;" ::: "memory");
        else            asm volatile("cp.async.wait_group 1;" ::: "memory");
        __syncthreads();
        uint32_t Ab = sb + (uint32_t)(t & 1) * 32768u;
        uint32_t Bb = Ab + 16384u;
#pragma unroll
        for (int kk = 0; kk < 4; kk++) {
            uint32_t a[2][4];
#pragma unroll
            for (int mi = 0; mi < 2; mi++) {
                int rr = wm * 32 + mi * 16 + (lane & 15);
                int byt = kk * 32 + ((lane >> 4) << 4);
                uint32_t ad = Ab + SWZ((uint32_t)(rr * 128 + byt));
                asm volatile("ldmatrix.sync.aligned.m8n8.x4.shared.b16 {%0,%1,%2,%3}, [%4];"
                    : "=r"(a[mi][0]), "=r"(a[mi][1]), "=r"(a[mi][2]), "=r"(a[mi][3])
                    : "r"(ad));
            }
            uint32_t b[8][2];
#pragma unroll
            for (int nj = 0; nj < 4; nj++) {
                int nn = wn * 64 + nj * 16 + ((lane >> 4) << 3) + (lane & 7);
                int byt = kk * 32 + (((lane >> 3) & 1) << 4);
                uint32_t bd2 = Bb + SWZ((uint32_t)(nn * 128 + byt));
                asm volatile("ldmatrix.sync.aligned.m8n8.x4.shared.b16 {%0,%1,%2,%3}, [%4];"
                    : "=r"(b[nj * 2][0]), "=r"(b[nj * 2][1]),
                      "=r"(b[nj * 2 + 1][0]), "=r"(b[nj * 2 + 1][1])
                    : "r"(bd2));
            }
#pragma unroll
            for (int mi = 0; mi < 2; mi++)
#pragma unroll
                for (int ni = 0; ni < 8; ni++) {
                    asm volatile(
                        "mma.sync.aligned.m16n8k16.row.col.f32.bf16.bf16.f32 "
                        "{%0,%1,%2,%3}, {%4,%5,%6,%7}, {%8,%9}, {%0,%1,%2,%3};"
                        : "+f"(acc[mi][ni][0]), "+f"(acc[mi][ni][1]),
                          "+f"(acc[mi][ni][2]), "+f"(acc[mi][ni][3])
                        : "r"(a[mi][0]), "r"(a[mi][1]), "r"(a[mi][2]), "r"(a[mi][3]),
                          "r"(b[ni][0]), "r"(b[ni][1]));
                }
        }
        __syncthreads();
        if (t + 2 < C) issue(t + 2);
    }

    // epilogue straight from fragments
    int lr = lane >> 2, lc = (lane & 3) * 2;
#pragma unroll
    for (int mi = 0; mi < 2; mi++)
#pragma unroll
        for (int half = 0; half < 2; half++) {
            int row = row0 + wm * 32 + mi * 16 + half * 8 + lr;
            if (row < g.M) {
#pragma unroll
                for (int ni = 0; ni < 8; ni++) {
                    int c = col0 + wn * 64 + ni * 8 + lc;
                    epi_pair(g, row, c, acc[mi][ni][half * 2], acc[mi][ni][half * 2 + 1]);
                }
            }
        }
}

// ---------------------------------------------------------------------------
extern "C" void kernel_launch(void* const* d_in, const int* in_sizes, int n_in,
                              void* d_out, int out_size) {
    const float* x_user = (const float*)d_in[0];
    const float* x_news = (const float*)d_in[1];
    const float* h_user = (const float*)d_in[2];
    const float* h_news = (const float*)d_in[3];
    const float* Wl     = (const float*)d_in[4];
    const float* Wr     = (const float*)d_in[5];
    const float* bb     = (const float*)d_in[6];
    const int* src_un   = (const int*)d_in[7];
    const int* dst_un   = (const int*)d_in[8];
    const int* src_nu   = (const int*)d_in[9];
    const int* dst_nu   = (const int*)d_in[10];

    int NU = in_sizes[0] / D;
    int NN = in_sizes[1] / D;
    int E1 = in_sizes[7];
    int E2 = in_sizes[9];

    float* base = nullptr;
    int* deg = nullptr;
    cudaGetSymbolAddress((void**)&base, g_buf);
    cudaGetSymbolAddress((void**)&deg, g_deg);

    float* Axn = base + 0 * SZF;
    float* Ahn = base + 1 * SZF;
    float* Axu = base + 2 * SZF;
    float* Ahu = base + 3 * SZF;
    float* Acn = base + 4 * SZF;
    float* Acu = base + 5 * SZF;
    float* Zn  = base + 6 * SZF;
    float* Zu  = base + 7 * SZF;
    float* CXn = base + 8 * SZF;
    float* CXu = base + 9 * SZF;
    // packed: 0 PXU, 1 PXN, 2 PHU, 3 PHN, 4 PAXN, 5 PAHN, 6 PAXU, 7 PAHU,
    //         8 PACN, 9 PACU, 10 PHRN, 11 PHRU
    auto packP = [&](int idx) -> char* { return (char*)(base + (10L + idx) * SZF); };

    float* wf = base + 22 * SZF;
    char* WzrN = (char*)(wf);
    char* WzrU = (char*)(wf + 131072);
    char* WcxN = (char*)(wf + 262144);
    char* WcxU = (char*)(wf + 262144 + 32768);
    char* WchN = (char*)(wf + 262144 + 2 * 32768);
    char* WchU = (char*)(wf + 262144 + 3 * 32768);
    float* bzr_n = wf + 262144 + 4 * 32768;
    float* bzr_u = bzr_n + 256;
    float* bcx_n = bzr_u + 256;
    float* bcx_u = bcx_n + 128;
    float* bch_n = bcx_u + 128;
    float* bch_u = bch_n + 128;

    int* deg_n = deg;
    int* deg_u = deg + MAXN;

    float* out_u = (float*)d_out;
    float* out_n = (float*)d_out + (long)NU * D;

    long MbU = (long)NU * 128, MbN = (long)NN * 128;

    cudaFuncSetAttribute(gemm_mma, cudaFuncAttributeMaxDynamicSharedMemorySize, 65536);

    zero_kernel<<<2048, 256>>>((float4*)base, (6 * SZF) / 4, deg, 2 * MAXN);

    pack_w_zr<<<512, 256>>>(Wl, Wr, WzrN, 0);
    pack_w_zr<<<512, 256>>>(Wl, Wr, WzrU, 1);
    pack_w2<<<128, 256>>>(Wl, Wr, WcxN, 4, 0);
    pack_w2<<<128, 256>>>(Wl, Wr, WcxU, 4, 1);
    pack_w2<<<128, 256>>>(Wl, Wr, WchN, 5, 0);
    pack_w2<<<128, 256>>>(Wl, Wr, WchU, 5, 1);
    build_bias<<<1, 128>>>(bb, bzr_n, bzr_u, bcx_n, bcx_u, bch_n, bch_u);

    pack_kernel<<<(NU * 32 + 255) / 256, 256>>>(x_user, nullptr, NU, packP(0));
    pack_kernel<<<(NN * 32 + 255) / 256, 256>>>(x_news, nullptr, NN, packP(1));
    pack_kernel<<<(NU * 32 + 255) / 256, 256>>>(h_user, nullptr, NU, packP(2));
    pack_kernel<<<(NN * 32 + 255) / 256, 256>>>(h_news, nullptr, NN, packP(3));

    count_deg<<<(E1 + 255) / 256, 256>>>(dst_un, E1, deg_n);
    count_deg<<<(E2 + 255) / 256, 256>>>(dst_nu, E2, deg_u);
    long t1 = (long)E1 * 32, t2 = (long)E2 * 32;
    agg2_kernel<<<(int)((t1 + 255) / 256), 256>>>(x_user, h_user, src_un, dst_un, E1, Axn, Ahn);
    agg2_kernel<<<(int)((t2 + 255) / 256), 256>>>(x_news, h_news, src_nu, dst_nu, E2, Axu, Ahu);

    pack_kernel<<<(NN * 32 + 255) / 256, 256>>>(Axn, deg_n, NN, packP(4));
    pack_kernel<<<(NN * 32 + 255) / 256, 256>>>(Ahn, deg_n, NN, packP(5));
    pack_kernel<<<(NU * 32 + 255) / 256, 256>>>(Axu, deg_u, NU, packP(6));
    pack_kernel<<<(NU * 32 + 255) / 256, 256>>>(Ahu, deg_u, NU, packP(7));

    // z|r GEMMs (N=256): sigmoid + h*r repack epilogue
    {
        GP g{};
        g.hi[0] = packP(4); g.hi[1] = packP(1); g.hi[2] = packP(5); g.hi[3] = packP(3);
        for (int p = 0; p < 4; p++) g.lo[p] = g.hi[p] + 2 * MbN;
        g.B = WzrN; g.bias = bzr_n; g.H = h_news; g.out0 = Zn; g.outHR = packP(10);
        g.Mb = MbN; g.M = NN; g.N = 256; g.nparts = 4; g.mode = 0;
        gemm_mma<<<dim3((NN + 127) / 128, 2), 256, 65536>>>(g);
    }
    {
        GP g{};
        g.hi[0] = packP(6); g.hi[1] = packP(0); g.hi[2] = packP(7); g.hi[3] = packP(2);
        for (int p = 0; p < 4; p++) g.lo[p] = g.hi[p] + 2 * MbU;
        g.B = WzrU; g.bias = bzr_u; g.H = h_user; g.out0 = Zu; g.outHR = packP(11);
        g.Mb = MbU; g.M = NU; g.N = 256; g.nparts = 4; g.mode = 0;
        gemm_mma<<<dim3((NU + 127) / 128, 2), 256, 65536>>>(g);
    }

    // cx GEMMs (N=128)
    {
        GP g{};
        g.hi[0] = packP(4); g.hi[1] = packP(1);
        g.lo[0] = g.hi[0] + 2 * MbN; g.lo[1] = g.hi[1] + 2 * MbN;
        g.B = WcxN; g.bias = bcx_n; g.out0 = CXn;
        g.Mb = MbN; g.M = NN; g.N = 128; g.nparts = 2; g.mode = 1;
        gemm_mma<<<dim3((NN + 127) / 128, 1), 256, 65536>>>(g);
    }
    {
        GP g{};
        g.hi[0] = packP(6); g.hi[1] = packP(0);
        g.lo[0] = g.hi[0] + 2 * MbU; g.lo[1] = g.hi[1] + 2 * MbU;
        g.B = WcxU; g.bias = bcx_u; g.out0 = CXu;
        g.Mb = MbU; g.M = NU; g.N = 128; g.nparts = 2; g.mode = 1;
        gemm_mma<<<dim3((NU + 127) / 128, 1), 256, 65536>>>(g);
    }

    // aggregate h*r from packed HR
    agg1_packed<<<(int)((t1 + 255) / 256), 256>>>(packP(11), MbU, src_un, dst_un, E1, Acn);
    agg1_packed<<<(int)((t2 + 255) / 256), 256>>>(packP(10), MbN, src_nu, dst_nu, E2, Acu);
    pack_kernel<<<(NN * 32 + 255) / 256, 256>>>(Acn, deg_n, NN, packP(8));
    pack_kernel<<<(NU * 32 + 255) / 256, 256>>>(Acu, deg_u, NU, packP(9));

    // ch GEMMs: tanh + GRU update fused into d_out
    {
        GP g{};
        g.hi[0] = packP(9); g.hi[1] = packP(11);
        g.lo[0] = g.hi[0] + 2 * MbU; g.lo[1] = g.hi[1] + 2 * MbU;
        g.B = WchU; g.bias = bch_u; g.H = h_user; g.Z = Zu; g.CX = CXu; g.out0 = out_u;
        g.Mb = MbU; g.M = NU; g.N = 128; g.nparts = 2; g.mode = 2;
        gemm_mma<<<dim3((NU + 127) / 128, 1), 256, 65536>>>(g);
    }
    {
        GP g{};
        g.hi[0] = packP(8); g.hi[1] = packP(10);
        g.lo[0] = g.hi[0] + 2 * MbN; g.lo[1] = g.hi[1] + 2 * MbN;
        g.B = WchN; g.bias = bch_n; g.H = h_news; g.Z = Zn; g.CX = CXn; g.out0 = out_n;
        g.Mb = MbN; g.M = NN; g.N = 128; g.nparts = 2; g.mode = 2;
        gemm_mma<<<dim3((NN + 127) / 128, 1), 256, 65536>>>(g);
    }
}

// round 5
// speedup vs baseline: 1.8721x; 1.1291x over previous
#include <cuda_runtime.h>
#include <cuda_bf16.h>
#include <math.h>
#include <stdint.h>

#define D 128
#define MAXN 50000
#define SZF (50000L * 128L)

// fp32: Axn Ahn Axu Ahu Acn Acu Zn Zu CXn CXu (10*SZF)
// packed bf16 hi/lo regions: 12*SZF ; weights+bias tail
__device__ float g_buf[22L * SZF + 2 * 131072 + 4 * 32768 + 1024];
__device__ int g_deg[2 * MAXN];

// ---------------- helpers ----------------
__device__ __forceinline__ uint32_t s2u(const void* p) {
    uint32_t a;
    asm("{ .reg .u64 t; cvta.to.shared.u64 t, %1; cvt.u32.u64 %0, t; }" : "=r"(a) : "l"(p));
    return a;
}
__device__ __host__ __forceinline__ uint32_t SWZ(uint32_t x) { return x ^ ((x >> 3) & 0x70); }

__device__ __forceinline__ float sigf(float x) { return 1.f / (1.f + expf(-x)); }

__device__ __forceinline__ void split4(float4 v, uint2& hu, uint2& lu) {
    __nv_bfloat162 h01 = __floats2bfloat162_rn(v.x, v.y);
    __nv_bfloat162 h23 = __floats2bfloat162_rn(v.z, v.w);
    float lx = v.x - __bfloat162float(__low2bfloat16(h01));
    float ly = v.y - __bfloat162float(__high2bfloat16(h01));
    float lz = v.z - __bfloat162float(__low2bfloat16(h23));
    float lw = v.w - __bfloat162float(__high2bfloat16(h23));
    __nv_bfloat162 l01 = __floats2bfloat162_rn(lx, ly);
    __nv_bfloat162 l23 = __floats2bfloat162_rn(lz, lw);
    hu.x = *reinterpret_cast<uint32_t*>(&h01);
    hu.y = *reinterpret_cast<uint32_t*>(&h23);
    lu.x = *reinterpret_cast<uint32_t*>(&l01);
    lu.y = *reinterpret_cast<uint32_t*>(&l23);
}

__device__ __forceinline__ void split2(float x, float y, uint32_t& hw, uint32_t& lw) {
    __nv_bfloat162 h = __floats2bfloat162_rn(x, y);
    float rx = x - __bfloat162float(__low2bfloat16(h));
    float ry = y - __bfloat162float(__high2bfloat16(h));
    __nv_bfloat162 l = __floats2bfloat162_rn(rx, ry);
    hw = *reinterpret_cast<uint32_t*>(&h);
    lw = *reinterpret_cast<uint32_t*>(&l);
}

// ---------------- simple kernels ----------------
__global__ void zero_kernel(float4* p, long n4, int* d, int nd) {
    long stride = (long)gridDim.x * blockDim.x;
    long i0 = blockIdx.x * (long)blockDim.x + threadIdx.x;
    for (long j = i0; j < n4; j += stride) p[j] = make_float4(0.f, 0.f, 0.f, 0.f);
    for (long j = i0; j < nd; j += stride) d[j] = 0;
}

// warp-per-edge scatter of x and h rows + degree bump (fused)
__global__ void agg2_kernel(const float* __restrict__ fx, const float* __restrict__ fh,
                            const int* __restrict__ src, const int* __restrict__ dst, int E,
                            float* __restrict__ Ax, float* __restrict__ Ah,
                            int* __restrict__ deg) {
    long gid = blockIdx.x * (long)blockDim.x + threadIdx.x;
    int e = (int)(gid >> 5);
    int lane = (int)(gid & 31);
    if (e >= E) return;
    int s = src[e], d = dst[e];
    float4 vx = *(const float4*)(fx + (long)s * D + lane * 4);
    float4 vh = *(const float4*)(fh + (long)s * D + lane * 4);
    atomicAdd((float4*)(Ax + (long)d * D + lane * 4), vx);
    atomicAdd((float4*)(Ah + (long)d * D + lane * 4), vh);
    if (lane == 0) atomicAdd(&deg[d], 1);
}

// gather packed hi/lo bf16 rows (reconstruct fp32), scatter-add
__global__ void agg1_packed(const char* __restrict__ P, long Mb,
                            const int* __restrict__ src, const int* __restrict__ dst, int E,
                            float* __restrict__ A) {
    long gid = blockIdx.x * (long)blockDim.x + threadIdx.x;
    int e = (int)(gid >> 5);
    int lane = (int)(gid & 31);
    if (e >= E) return;
    int s = src[e], d = dst[e];
    int c4 = lane * 4;
    int q = c4 >> 6;
    int inner = c4 & 63;
    uint32_t sw = SWZ((uint32_t)s * 128u + (uint32_t)inner * 2u);
    uint2 hu = *(const uint2*)(P + (long)q * Mb + sw);
    uint2 lu = *(const uint2*)(P + 2 * Mb + (long)q * Mb + sw);
    float2 a = __bfloat1622float2(*reinterpret_cast<__nv_bfloat162*>(&hu.x));
    float2 b = __bfloat1622float2(*reinterpret_cast<__nv_bfloat162*>(&hu.y));
    float2 c = __bfloat1622float2(*reinterpret_cast<__nv_bfloat162*>(&lu.x));
    float2 dd = __bfloat1622float2(*reinterpret_cast<__nv_bfloat162*>(&lu.y));
    float4 v = make_float4(a.x + c.x, a.y + c.y, b.x + dd.x, b.y + dd.y);
    atomicAdd((float4*)(A + (long)d * D + c4), v);
}

// fp32 [M,128] (* 1/deg optional) -> packed hi/lo bf16 SW128 chunks
__global__ void pack_kernel(const float* __restrict__ src, const int* __restrict__ deg,
                            int M, char* __restrict__ dst) {
    long i = blockIdx.x * (long)blockDim.x + threadIdx.x;
    if (i >= (long)M * 32) return;
    int row = (int)(i >> 5);
    int c4 = ((int)i & 31) * 4;
    float inv = 1.f;
    if (deg) inv = 1.f / (float)max(deg[row], 1);
    float4 v = ((const float4*)src)[i];
    v.x *= inv; v.y *= inv; v.z *= inv; v.w *= inv;
    uint2 hu, lu;
    split4(v, hu, lu);
    int q = c4 >> 6;
    int inner = c4 & 63;
    uint32_t sw = SWZ((uint32_t)row * 128u + (uint32_t)inner * 2u);
    long Mb = (long)M * 128;
    *(uint2*)(dst + (long)q * Mb + sw) = hu;
    *(uint2*)(dst + 2 * Mb + (long)q * Mb + sw) = lu;
}

// ---------------- weight packing ----------------
__global__ void pack_w_zr(const float* __restrict__ Wl, const float* __restrict__ Wr,
                          char* __restrict__ dst, int t) {
    int j = blockIdx.x * blockDim.x + threadIdx.x;
    if (j >= 4 * 256 * 128) return;
    int k = j & 127;
    int n = (j >> 7) & 255;
    int p = j >> 15;
    int gz = (n < 128) ? 0 : 2;
    int cc = n & 127;
    int g = gz + (p >> 1);
    const float* S = (p & 1) ? Wr : Wl;
    float w = S[((long)(g * 2 + t) * 128 + k) * 128 + cc];
    __nv_bfloat16 h = __float2bfloat16_rn(w);
    float lof = w - __bfloat162float(h);
    __nv_bfloat16 l = __float2bfloat16_rn(lof);
    int q = k >> 6;
    int inner = k & 63;
    uint32_t sw = SWZ((uint32_t)n * 128u + (uint32_t)inner * 2u);
    const int Nb = 256 * 128;
    *(unsigned short*)(dst + (size_t)((p * 2 + 0) * 2 + q) * Nb + sw) = *reinterpret_cast<unsigned short*>(&h);
    *(unsigned short*)(dst + (size_t)((p * 2 + 1) * 2 + q) * Nb + sw) = *reinterpret_cast<unsigned short*>(&l);
}

__global__ void pack_w2(const float* __restrict__ Wl, const float* __restrict__ Wr,
                        char* __restrict__ dst, int g, int t) {
    int j = blockIdx.x * blockDim.x + threadIdx.x;
    if (j >= 2 * 128 * 128) return;
    int k = j & 127;
    int n = (j >> 7) & 127;
    int p = j >> 14;
    const float* S = p ? Wr : Wl;
    float w = S[((long)(g * 2 + t) * 128 + k) * 128 + n];
    __nv_bfloat16 h = __float2bfloat16_rn(w);
    float lof = w - __bfloat162float(h);
    __nv_bfloat16 l = __float2bfloat16_rn(lof);
    int q = k >> 6;
    int inner = k & 63;
    uint32_t sw = SWZ((uint32_t)n * 128u + (uint32_t)inner * 2u);
    const int Nb = 128 * 128;
    *(unsigned short*)(dst + (size_t)((p * 2 + 0) * 2 + q) * Nb + sw) = *reinterpret_cast<unsigned short*>(&h);
    *(unsigned short*)(dst + (size_t)((p * 2 + 1) * 2 + q) * Nb + sw) = *reinterpret_cast<unsigned short*>(&l);
}

__global__ void build_bias(const float* __restrict__ b,
                           float* bzr_n, float* bzr_u, float* bcx_n, float* bcx_u,
                           float* bch_n, float* bch_u) {
    int c = threadIdx.x;
    if (c >= 128) return;
#define BB(g, t) b[((g) * 2 + (t)) * 128 + c]
    bzr_n[c]       = BB(0, 0) + BB(1, 0);
    bzr_n[128 + c] = BB(2, 0) + BB(3, 0);
    bzr_u[c]       = BB(0, 1) + BB(1, 1);
    bzr_u[128 + c] = BB(2, 1) + BB(3, 1);
    bcx_n[c] = BB(4, 0);
    bcx_u[c] = BB(4, 1);
    bch_n[c] = BB(5, 0);
    bch_u[c] = BB(5, 1);
#undef BB
}

// ---------------- HMMA GEMM (mma.sync + ldmatrix + cp.async, 3-stage) ------
struct GP {
    const char* hi[4];
    const char* lo[4];
    const char* B;
    const float* bias;
    const float* H;
    const float* Z;
    const float* CX;
    float* out0;
    char* outHR;
    long Mb;
    int M, N, nparts, mode;   // mode 0=zr, 1=cx, 2=ch
};

__device__ __forceinline__ void epi_pair(const GP& g, int row, int c, float v0, float v1) {
    v0 += g.bias[c];
    v1 += g.bias[c + 1];
    long rb = (long)row * D;
    if (g.mode == 0) {
        if (c < 128) {
            g.out0[rb + c] = sigf(v0);
            g.out0[rb + c + 1] = sigf(v1);
        } else {
            int cc = c - 128;
            float r0 = sigf(v0) * g.H[rb + cc];
            float r1 = sigf(v1) * g.H[rb + cc + 1];
            uint32_t hw, lw;
            split2(r0, r1, hw, lw);
            uint32_t sw = SWZ((uint32_t)row * 128u + (uint32_t)(cc & 63) * 2u);
            int q = cc >> 6;
            *(uint32_t*)(g.outHR + (long)q * g.Mb + sw) = hw;
            *(uint32_t*)(g.outHR + 2 * g.Mb + (long)q * g.Mb + sw) = lw;
        }
    } else if (g.mode == 1) {
        g.out0[rb + c] = v0;
        g.out0[rb + c + 1] = v1;
    } else {
        float z0 = g.Z[rb + c], z1 = g.Z[rb + c + 1];
        float h0 = g.H[rb + c], h1 = g.H[rb + c + 1];
        float t0 = tanhf(v0 + g.CX[rb + c]);
        float t1 = tanhf(v1 + g.CX[rb + c + 1]);
        g.out0[rb + c] = z0 * h0 + (1.f - z0) * t0;
        g.out0[rb + c + 1] = z1 * h1 + (1.f - z1) * t1;
    }
}

__global__ void __launch_bounds__(256) gemm_mma(GP g) {
    extern __shared__ char smem[];
    uint32_t sb = s2u(smem);
    int tid = threadIdx.x;
    int lane = tid & 31, wid = tid >> 5;
    int wm = wid & 3, wn = wid >> 2;          // 4x2 warp grid
    int row0 = blockIdx.x * 128;
    int col0 = blockIdx.y * 128;
    long Nb = (long)g.N * 128;
    int C = g.nparts * 6;                      // stages: parts x 3 terms x 2 chunks

    float acc[2][8][4];
#pragma unroll
    for (int i = 0; i < 2; i++)
#pragma unroll
        for (int j = 0; j < 8; j++)
#pragma unroll
            for (int k = 0; k < 4; k++) acc[i][j][k] = 0.f;

    auto issue = [&](int t) {
        int buf = t % 3;
        int p = t / 6, r = t % 6, sec = r >> 1, q = r & 1;
        const char* Asrc = ((sec == 1) ? g.lo[p] : g.hi[p]) + (long)q * g.Mb + (long)row0 * 128;
        const char* Bsrc = g.B + (size_t)((p * 2 + (sec == 2 ? 1 : 0)) * 2 + q) * Nb
                         + (long)col0 * 128;
        uint32_t Ad = sb + (uint32_t)buf * 32768u;
        uint32_t Bd = Ad + 16384u;
#pragma unroll
        for (int j = 0; j < 4; j++) {
            int idx = tid + j * 256;
            uint32_t sz = (row0 + (idx >> 3) < g.M) ? 16u : 0u;
            asm volatile("cp.async.cg.shared.global [%0], [%1], 16, %2;"
                         :: "r"(Ad + idx * 16), "l"(Asrc + (long)idx * 16), "r"(sz));
        }
#pragma unroll
        for (int j = 0; j < 4; j++) {
            int idx = tid + j * 256;
            asm volatile("cp.async.cg.shared.global [%0], [%1], 16;"
                         :: "r"(Bd + idx * 16), "l"(Bsrc + (long)idx * 16));
        }
        asm volatile("cp.async.commit_group;" ::: "memory");
    };

    issue(0);
    issue(1);
    issue(2);

    for (int t = 0; t < C; t++) {
        int rem = C - t;
        if (rem > 2)       asm volatile("cp.async.wait_group 2;" ::: "memory");
        else if (rem == 2) asm volatile("cp.async.wait_group 1;" ::: "memory");
        else               asm volatile("cp.async.wait_group 0;" ::: "memory");
        __syncthreads();
        uint32_t Ab = sb + (uint32_t)(t % 3) * 32768u;
        uint32_t Bb = Ab + 16384u;
#pragma unroll
        for (int kk = 0; kk < 4; kk++) {
            uint32_t a[2][4];
#pragma unroll
            for (int mi = 0; mi < 2; mi++) {
                int rr = wm * 32 + mi * 16 + (lane & 15);
                int byt = kk * 32 + ((lane >> 4) << 4);
                uint32_t ad = Ab + SWZ((uint32_t)(rr * 128 + byt));
                asm volatile("ldmatrix.sync.aligned.m8n8.x4.shared.b16 {%0,%1,%2,%3}, [%4];"
                    : "=r"(a[mi][0]), "=r"(a[mi][1]), "=r"(a[mi][2]), "=r"(a[mi][3])
                    : "r"(ad));
            }
            uint32_t b[8][2];
#pragma unroll
            for (int nj = 0; nj < 4; nj++) {
                int nn = wn * 64 + nj * 16 + ((lane >> 4) << 3) + (lane & 7);
                int byt = kk * 32 + (((lane >> 3) & 1) << 4);
                uint32_t bd2 = Bb + SWZ((uint32_t)(nn * 128 + byt));
                asm volatile("ldmatrix.sync.aligned.m8n8.x4.shared.b16 {%0,%1,%2,%3}, [%4];"
                    : "=r"(b[nj * 2][0]), "=r"(b[nj * 2][1]),
                      "=r"(b[nj * 2 + 1][0]), "=r"(b[nj * 2 + 1][1])
                    : "r"(bd2));
            }
#pragma unroll
            for (int mi = 0; mi < 2; mi++)
#pragma unroll
                for (int ni = 0; ni < 8; ni++) {
                    asm volatile(
                        "mma.sync.aligned.m16n8k16.row.col.f32.bf16.bf16.f32 "
                        "{%0,%1,%2,%3}, {%4,%5,%6,%7}, {%8,%9}, {%0,%1,%2,%3};"
                        : "+f"(acc[mi][ni][0]), "+f"(acc[mi][ni][1]),
                          "+f"(acc[mi][ni][2]), "+f"(acc[mi][ni][3])
                        : "r"(a[mi][0]), "r"(a[mi][1]), "r"(a[mi][2]), "r"(a[mi][3]),
                          "r"(b[ni][0]), "r"(b[ni][1]));
                }
        }
        __syncthreads();
        if (t + 3 < C) issue(t + 3);
    }

    // epilogue straight from fragments
    int lr = lane >> 2, lc = (lane & 3) * 2;
#pragma unroll
    for (int mi = 0; mi < 2; mi++)
#pragma unroll
        for (int half = 0; half < 2; half++) {
            int row = row0 + wm * 32 + mi * 16 + half * 8 + lr;
            if (row < g.M) {
#pragma unroll
                for (int ni = 0; ni < 8; ni++) {
                    int c = col0 + wn * 64 + ni * 8 + lc;
                    epi_pair(g, row, c, acc[mi][ni][half * 2], acc[mi][ni][half * 2 + 1]);
                }
            }
        }
}

// ---------------------------------------------------------------------------
extern "C" void kernel_launch(void* const* d_in, const int* in_sizes, int n_in,
                              void* d_out, int out_size) {
    const float* x_user = (const float*)d_in[0];
    const float* x_news = (const float*)d_in[1];
    const float* h_user = (const float*)d_in[2];
    const float* h_news = (const float*)d_in[3];
    const float* Wl     = (const float*)d_in[4];
    const float* Wr     = (const float*)d_in[5];
    const float* bb     = (const float*)d_in[6];
    const int* src_un   = (const int*)d_in[7];
    const int* dst_un   = (const int*)d_in[8];
    const int* src_nu   = (const int*)d_in[9];
    const int* dst_nu   = (const int*)d_in[10];

    int NU = in_sizes[0] / D;
    int NN = in_sizes[1] / D;
    int E1 = in_sizes[7];
    int E2 = in_sizes[9];

    float* base = nullptr;
    int* deg = nullptr;
    cudaGetSymbolAddress((void**)&base, g_buf);
    cudaGetSymbolAddress((void**)&deg, g_deg);

    float* Axn = base + 0 * SZF;
    float* Ahn = base + 1 * SZF;
    float* Axu = base + 2 * SZF;
    float* Ahu = base + 3 * SZF;
    float* Acn = base + 4 * SZF;
    float* Acu = base + 5 * SZF;
    float* Zn  = base + 6 * SZF;
    float* Zu  = base + 7 * SZF;
    float* CXn = base + 8 * SZF;
    float* CXu = base + 9 * SZF;
    auto packP = [&](int idx) -> char* { return (char*)(base + (10L + idx) * SZF); };

    float* wf = base + 22 * SZF;
    char* WzrN = (char*)(wf);
    char* WzrU = (char*)(wf + 131072);
    char* WcxN = (char*)(wf + 262144);
    char* WcxU = (char*)(wf + 262144 + 32768);
    char* WchN = (char*)(wf + 262144 + 2 * 32768);
    char* WchU = (char*)(wf + 262144 + 3 * 32768);
    float* bzr_n = wf + 262144 + 4 * 32768;
    float* bzr_u = bzr_n + 256;
    float* bcx_n = bzr_u + 256;
    float* bcx_u = bcx_n + 128;
    float* bch_n = bcx_u + 128;
    float* bch_u = bch_n + 128;

    int* deg_n = deg;
    int* deg_u = deg + MAXN;

    float* out_u = (float*)d_out;
    float* out_n = (float*)d_out + (long)NU * D;

    long MbU = (long)NU * 128, MbN = (long)NN * 128;

    cudaFuncSetAttribute(gemm_mma, cudaFuncAttributeMaxDynamicSharedMemorySize, 98304);

    // second stream + events for fork/join (created per call; host-only objects,
    // intentionally not destroyed while capture is active)
    cudaStream_t s1;
    cudaStreamCreateWithFlags(&s1, cudaStreamNonBlocking);
    cudaEvent_t evPre, evHRn, evHRu, evJoin;
    cudaEventCreateWithFlags(&evPre, cudaEventDisableTiming);
    cudaEventCreateWithFlags(&evHRn, cudaEventDisableTiming);
    cudaEventCreateWithFlags(&evHRu, cudaEventDisableTiming);
    cudaEventCreateWithFlags(&evJoin, cudaEventDisableTiming);

    long t1 = (long)E1 * 32, t2 = (long)E2 * 32;

    // ---- shared preamble on default stream (S0) ----
    zero_kernel<<<2048, 256>>>((float4*)base, (6 * SZF) / 4, deg, 2 * MAXN);
    build_bias<<<1, 128>>>(bb, bzr_n, bzr_u, bcx_n, bcx_u, bch_n, bch_u);
    cudaEventRecord(evPre, 0);
    cudaStreamWaitEvent(s1, evPre, 0);

    // ---- S0: news chain ----
    pack_w_zr<<<512, 256>>>(Wl, Wr, WzrN, 0);
    pack_w2<<<128, 256>>>(Wl, Wr, WcxN, 4, 0);
    pack_w2<<<128, 256>>>(Wl, Wr, WchN, 5, 0);
    pack_kernel<<<(NN * 32 + 255) / 256, 256>>>(x_news, nullptr, NN, packP(1));
    pack_kernel<<<(NN * 32 + 255) / 256, 256>>>(h_news, nullptr, NN, packP(3));
    agg2_kernel<<<(int)((t1 + 255) / 256), 256>>>(x_user, h_user, src_un, dst_un, E1,
                                                  Axn, Ahn, deg_n);
    pack_kernel<<<(NN * 32 + 255) / 256, 256>>>(Axn, deg_n, NN, packP(4));
    pack_kernel<<<(NN * 32 + 255) / 256, 256>>>(Ahn, deg_n, NN, packP(5));

    // ---- S1: user chain ----
    pack_w_zr<<<512, 256, 0, s1>>>(Wl, Wr, WzrU, 1);
    pack_w2<<<128, 256, 0, s1>>>(Wl, Wr, WcxU, 4, 1);
    pack_w2<<<128, 256, 0, s1>>>(Wl, Wr, WchU, 5, 1);
    pack_kernel<<<(NU * 32 + 255) / 256, 256, 0, s1>>>(x_user, nullptr, NU, packP(0));
    pack_kernel<<<(NU * 32 + 255) / 256, 256, 0, s1>>>(h_user, nullptr, NU, packP(2));
    agg2_kernel<<<(int)((t2 + 255) / 256), 256, 0, s1>>>(x_news, h_news, src_nu, dst_nu, E2,
                                                         Axu, Ahu, deg_u);
    pack_kernel<<<(NU * 32 + 255) / 256, 256, 0, s1>>>(Axu, deg_u, NU, packP(6));
    pack_kernel<<<(NU * 32 + 255) / 256, 256, 0, s1>>>(Ahu, deg_u, NU, packP(7));

    // ---- zr GEMMs ----
    {
        GP g{};
        g.hi[0] = packP(4); g.hi[1] = packP(1); g.hi[2] = packP(5); g.hi[3] = packP(3);
        for (int p = 0; p < 4; p++) g.lo[p] = g.hi[p] + 2 * MbN;
        g.B = WzrN; g.bias = bzr_n; g.H = h_news; g.out0 = Zn; g.outHR = packP(10);
        g.Mb = MbN; g.M = NN; g.N = 256; g.nparts = 4; g.mode = 0;
        gemm_mma<<<dim3((NN + 127) / 128, 2), 256, 98304>>>(g);
        cudaEventRecord(evHRn, 0);
    }
    {
        GP g{};
        g.hi[0] = packP(6); g.hi[1] = packP(0); g.hi[2] = packP(7); g.hi[3] = packP(2);
        for (int p = 0; p < 4; p++) g.lo[p] = g.hi[p] + 2 * MbU;
        g.B = WzrU; g.bias = bzr_u; g.H = h_user; g.out0 = Zu; g.outHR = packP(11);
        g.Mb = MbU; g.M = NU; g.N = 256; g.nparts = 4; g.mode = 0;
        gemm_mma<<<dim3((NU + 127) / 128, 2), 256, 98304, s1>>>(g);
        cudaEventRecord(evHRu, s1);
    }

    // ---- cx GEMMs ----
    {
        GP g{};
        g.hi[0] = packP(4); g.hi[1] = packP(1);
        g.lo[0] = g.hi[0] + 2 * MbN; g.lo[1] = g.hi[1] + 2 * MbN;
        g.B = WcxN; g.bias = bcx_n; g.out0 = CXn;
        g.Mb = MbN; g.M = NN; g.N = 128; g.nparts = 2; g.mode = 1;
        gemm_mma<<<dim3((NN + 127) / 128, 1), 256, 98304>>>(g);
    }
    {
        GP g{};
        g.hi[0] = packP(6); g.hi[1] = packP(0);
        g.lo[0] = g.hi[0] + 2 * MbU; g.lo[1] = g.hi[1] + 2 * MbU;
        g.B = WcxU; g.bias = bcx_u; g.out0 = CXu;
        g.Mb = MbU; g.M = NU; g.N = 128; g.nparts = 2; g.mode = 1;
        gemm_mma<<<dim3((NU + 127) / 128, 1), 256, 98304, s1>>>(g);
    }

    // ---- h*r aggregation (cross dependency) ----
    cudaStreamWaitEvent(0, evHRu, 0);   // S0 needs HRu (from user zr GEMM)
    agg1_packed<<<(int)((t1 + 255) / 256), 256>>>(packP(11), MbU, src_un, dst_un, E1, Acn);
    pack_kernel<<<(NN * 32 + 255) / 256, 256>>>(Acn, deg_n, NN, packP(8));

    cudaStreamWaitEvent(s1, evHRn, 0);  // S1 needs HRn (from news zr GEMM)
    agg1_packed<<<(int)((t2 + 255) / 256), 256, 0, s1>>>(packP(10), MbN, src_nu, dst_nu, E2, Acu);
    pack_kernel<<<(NU * 32 + 255) / 256, 256, 0, s1>>>(Acu, deg_u, NU, packP(9));

    // ---- ch GEMMs: tanh + GRU update fused into d_out ----
    {
        GP g{};
        g.hi[0] = packP(8); g.hi[1] = packP(10);
        g.lo[0] = g.hi[0] + 2 * MbN; g.lo[1] = g.hi[1] + 2 * MbN;
        g.B = WchN; g.bias = bch_n; g.H = h_news; g.Z = Zn; g.CX = CXn; g.out0 = out_n;
        g.Mb = MbN; g.M = NN; g.N = 128; g.nparts = 2; g.mode = 2;
        gemm_mma<<<dim3((NN + 127) / 128, 1), 256, 98304>>>(g);
    }
    {
        GP g{};
        g.hi[0] = packP(9); g.hi[1] = packP(11);
        g.lo[0] = g.hi[0] + 2 * MbU; g.lo[1] = g.hi[1] + 2 * MbU;
        g.B = WchU; g.bias = bch_u; g.H = h_user; g.Z = Zu; g.CX = CXu; g.out0 = out_u;
        g.Mb = MbU; g.M = NU; g.N = 128; g.nparts = 2; g.mode = 2;
        gemm_mma<<<dim3((NU + 127) / 128, 1), 256, 98304, s1>>>(g);
    }

    // ---- join ----
    cudaEventRecord(evJoin, s1);
    cudaStreamWaitEvent(0, evJoin, 0);
}

// round 6
// speedup vs baseline: 2.0274x; 1.0830x over previous
#include <cuda_runtime.h>
#include <cuda_fp16.h>
#include <math.h>
#include <stdint.h>

#define D 128
#define MAXN 50000
#define SZF (50000L * 128L)

// fp32: Axn Ahn Axu Ahu Acn Acu Zn Zu CXn CXu (10*SZF)
// packed fp16 hi/lo regions: 12*SZF ; weights+bias tail
__device__ float g_buf[22L * SZF + 2 * 131072 + 4 * 32768 + 1024];
__device__ int g_deg[2 * MAXN];

// ---------------- helpers ----------------
__device__ __forceinline__ uint32_t s2u(const void* p) {
    uint32_t a;
    asm("{ .reg .u64 t; cvta.to.shared.u64 t, %1; cvt.u32.u64 %0, t; }" : "=r"(a) : "l"(p));
    return a;
}
__device__ __host__ __forceinline__ uint32_t SWZ(uint32_t x) { return x ^ ((x >> 3) & 0x70); }

__device__ __forceinline__ float sigf(float x) { return 1.f / (1.f + expf(-x)); }

// fp32x4 -> fp16 hi (uint2) + fp16 lo (uint2); hi+lo reconstructs to ~2^-22
__device__ __forceinline__ void split4(float4 v, uint2& hu, uint2& lu) {
    __half2 h01 = __floats2half2_rn(v.x, v.y);
    __half2 h23 = __floats2half2_rn(v.z, v.w);
    float lx = v.x - __half2float(__low2half(h01));
    float ly = v.y - __half2float(__high2half(h01));
    float lz = v.z - __half2float(__low2half(h23));
    float lw = v.w - __half2float(__high2half(h23));
    __half2 l01 = __floats2half2_rn(lx, ly);
    __half2 l23 = __floats2half2_rn(lz, lw);
    hu.x = *reinterpret_cast<uint32_t*>(&h01);
    hu.y = *reinterpret_cast<uint32_t*>(&h23);
    lu.x = *reinterpret_cast<uint32_t*>(&l01);
    lu.y = *reinterpret_cast<uint32_t*>(&l23);
}

__device__ __forceinline__ void split2(float x, float y, uint32_t& hw, uint32_t& lw) {
    __half2 h = __floats2half2_rn(x, y);
    float rx = x - __half2float(__low2half(h));
    float ry = y - __half2float(__high2half(h));
    __half2 l = __floats2half2_rn(rx, ry);
    hw = *reinterpret_cast<uint32_t*>(&h);
    lw = *reinterpret_cast<uint32_t*>(&l);
}

// ---------------- simple kernels ----------------
__global__ void zero_kernel(float4* p, long n4, int* d, int nd) {
    long stride = (long)gridDim.x * blockDim.x;
    long i0 = blockIdx.x * (long)blockDim.x + threadIdx.x;
    for (long j = i0; j < n4; j += stride) p[j] = make_float4(0.f, 0.f, 0.f, 0.f);
    for (long j = i0; j < nd; j += stride) d[j] = 0;
}

// warp-per-edge scatter of x and h rows + degree bump (fused)
__global__ void agg2_kernel(const float* __restrict__ fx, const float* __restrict__ fh,
                            const int* __restrict__ src, const int* __restrict__ dst, int E,
                            float* __restrict__ Ax, float* __restrict__ Ah,
                            int* __restrict__ deg) {
    long gid = blockIdx.x * (long)blockDim.x + threadIdx.x;
    int e = (int)(gid >> 5);
    int lane = (int)(gid & 31);
    if (e >= E) return;
    int s = src[e], d = dst[e];
    float4 vx = *(const float4*)(fx + (long)s * D + lane * 4);
    float4 vh = *(const float4*)(fh + (long)s * D + lane * 4);
    atomicAdd((float4*)(Ax + (long)d * D + lane * 4), vx);
    atomicAdd((float4*)(Ah + (long)d * D + lane * 4), vh);
    if (lane == 0) atomicAdd(&deg[d], 1);
}

// gather packed hi/lo fp16 rows (reconstruct fp32), scatter-add
__global__ void agg1_packed(const char* __restrict__ P, long Mb,
                            const int* __restrict__ src, const int* __restrict__ dst, int E,
                            float* __restrict__ A) {
    long gid = blockIdx.x * (long)blockDim.x + threadIdx.x;
    int e = (int)(gid >> 5);
    int lane = (int)(gid & 31);
    if (e >= E) return;
    int s = src[e], d = dst[e];
    int c4 = lane * 4;
    int q = c4 >> 6;
    int inner = c4 & 63;
    uint32_t sw = SWZ((uint32_t)s * 128u + (uint32_t)inner * 2u);
    uint2 hu = *(const uint2*)(P + (long)q * Mb + sw);
    uint2 lu = *(const uint2*)(P + 2 * Mb + (long)q * Mb + sw);
    float2 a = __half22float2(*reinterpret_cast<__half2*>(&hu.x));
    float2 b = __half22float2(*reinterpret_cast<__half2*>(&hu.y));
    float2 c = __half22float2(*reinterpret_cast<__half2*>(&lu.x));
    float2 dd = __half22float2(*reinterpret_cast<__half2*>(&lu.y));
    float4 v = make_float4(a.x + c.x, a.y + c.y, b.x + dd.x, b.y + dd.y);
    atomicAdd((float4*)(A + (long)d * D + c4), v);
}

// fp32 [M,128] (* 1/deg optional) -> packed hi/lo fp16 SW128 chunks
__global__ void pack_kernel(const float* __restrict__ src, const int* __restrict__ deg,
                            int M, char* __restrict__ dst) {
    long i = blockIdx.x * (long)blockDim.x + threadIdx.x;
    if (i >= (long)M * 32) return;
    int row = (int)(i >> 5);
    int c4 = ((int)i & 31) * 4;
    float inv = 1.f;
    if (deg) inv = 1.f / (float)max(deg[row], 1);
    float4 v = ((const float4*)src)[i];
    v.x *= inv; v.y *= inv; v.z *= inv; v.w *= inv;
    uint2 hu, lu;
    split4(v, hu, lu);
    int q = c4 >> 6;
    int inner = c4 & 63;
    uint32_t sw = SWZ((uint32_t)row * 128u + (uint32_t)inner * 2u);
    long Mb = (long)M * 128;
    *(uint2*)(dst + (long)q * Mb + sw) = hu;
    *(uint2*)(dst + 2 * Mb + (long)q * Mb + sw) = lu;
}

// ---------------- weight packing (fp16, single term) ----------------
// zr: parts [Wl[gz],Wr[gz],Wl[gz+1],Wr[gz+1]], gz=(n<128)?0:2. B[n][k],
// blocks (p*2+q), each 256 rows x 128B, SW128.
__global__ void pack_w_zr(const float* __restrict__ Wl, const float* __restrict__ Wr,
                          char* __restrict__ dst, int t) {
    int j = blockIdx.x * blockDim.x + threadIdx.x;
    if (j >= 4 * 256 * 128) return;
    int k = j & 127;
    int n = (j >> 7) & 255;
    int p = j >> 15;
    int gz = (n < 128) ? 0 : 2;
    int cc = n & 127;
    int g = gz + (p >> 1);
    const float* S = (p & 1) ? Wr : Wl;
    float w = S[((long)(g * 2 + t) * 128 + k) * 128 + cc];
    __half h = __float2half_rn(w);
    int q = k >> 6;
    int inner = k & 63;
    uint32_t sw = SWZ((uint32_t)n * 128u + (uint32_t)inner * 2u);
    const int Nb = 256 * 128;
    *(unsigned short*)(dst + (size_t)(p * 2 + q) * Nb + sw) = *reinterpret_cast<unsigned short*>(&h);
}

__global__ void pack_w2(const float* __restrict__ Wl, const float* __restrict__ Wr,
                        char* __restrict__ dst, int g, int t) {
    int j = blockIdx.x * blockDim.x + threadIdx.x;
    if (j >= 2 * 128 * 128) return;
    int k = j & 127;
    int n = (j >> 7) & 127;
    int p = j >> 14;
    const float* S = p ? Wr : Wl;
    float w = S[((long)(g * 2 + t) * 128 + k) * 128 + n];
    __half h = __float2half_rn(w);
    int q = k >> 6;
    int inner = k & 63;
    uint32_t sw = SWZ((uint32_t)n * 128u + (uint32_t)inner * 2u);
    const int Nb = 128 * 128;
    *(unsigned short*)(dst + (size_t)(p * 2 + q) * Nb + sw) = *reinterpret_cast<unsigned short*>(&h);
}

__global__ void build_bias(const float* __restrict__ b,
                           float* bzr_n, float* bzr_u, float* bcx_n, float* bcx_u,
                           float* bch_n, float* bch_u) {
    int c = threadIdx.x;
    if (c >= 128) return;
#define BB(g, t) b[((g) * 2 + (t)) * 128 + c]
    bzr_n[c]       = BB(0, 0) + BB(1, 0);
    bzr_n[128 + c] = BB(2, 0) + BB(3, 0);
    bzr_u[c]       = BB(0, 1) + BB(1, 1);
    bzr_u[128 + c] = BB(2, 1) + BB(3, 1);
    bcx_n[c] = BB(4, 0);
    bcx_u[c] = BB(4, 1);
    bch_n[c] = BB(5, 0);
    bch_u[c] = BB(5, 1);
#undef BB
}

// ---------------- HMMA GEMM (fp16 2-term compensated, 3-stage cp.async) ----
struct GP {
    const char* hi[4];
    const char* lo[4];
    const char* B;
    const float* bias;
    const float* H;
    const float* Z;
    const float* CX;
    float* out0;
    char* outHR;
    long Mb;
    int M, N, nparts, mode;   // mode 0=zr, 1=cx, 2=ch
};

__device__ __forceinline__ void epi_pair(const GP& g, int row, int c, float v0, float v1) {
    v0 += g.bias[c];
    v1 += g.bias[c + 1];
    long rb = (long)row * D;
    if (g.mode == 0) {
        if (c < 128) {
            g.out0[rb + c] = sigf(v0);
            g.out0[rb + c + 1] = sigf(v1);
        } else {
            int cc = c - 128;
            float r0 = sigf(v0) * g.H[rb + cc];
            float r1 = sigf(v1) * g.H[rb + cc + 1];
            uint32_t hw, lw;
            split2(r0, r1, hw, lw);
            uint32_t sw = SWZ((uint32_t)row * 128u + (uint32_t)(cc & 63) * 2u);
            int q = cc >> 6;
            *(uint32_t*)(g.outHR + (long)q * g.Mb + sw) = hw;
            *(uint32_t*)(g.outHR + 2 * g.Mb + (long)q * g.Mb + sw) = lw;
        }
    } else if (g.mode == 1) {
        g.out0[rb + c] = v0;
        g.out0[rb + c + 1] = v1;
    } else {
        float z0 = g.Z[rb + c], z1 = g.Z[rb + c + 1];
        float h0 = g.H[rb + c], h1 = g.H[rb + c + 1];
        float t0 = tanhf(v0 + g.CX[rb + c]);
        float t1 = tanhf(v1 + g.CX[rb + c + 1]);
        g.out0[rb + c] = z0 * h0 + (1.f - z0) * t0;
        g.out0[rb + c + 1] = z1 * h1 + (1.f - z1) * t1;
    }
}

__global__ void __launch_bounds__(256) gemm_mma(GP g) {
    extern __shared__ char smem[];
    uint32_t sb = s2u(smem);
    int tid = threadIdx.x;
    int lane = tid & 31, wid = tid >> 5;
    int wm = wid & 3, wn = wid >> 2;          // 4x2 warp grid
    int row0 = blockIdx.x * 128;
    int col0 = blockIdx.y * 128;
    long Nb = (long)g.N * 128;
    int C = g.nparts * 4;                      // parts x 2 terms x 2 chunks

    float acc[2][8][4];
#pragma unroll
    for (int i = 0; i < 2; i++)
#pragma unroll
        for (int j = 0; j < 8; j++)
#pragma unroll
            for (int k = 0; k < 4; k++) acc[i][j][k] = 0.f;

    auto issue = [&](int t) {
        int buf = t % 3;
        int p = t >> 2, r = t & 3, term = r >> 1, q = r & 1;
        const char* Asrc = (term ? g.lo[p] : g.hi[p]) + (long)q * g.Mb + (long)row0 * 128;
        const char* Bsrc = g.B + (size_t)(p * 2 + q) * Nb + (long)col0 * 128;
        uint32_t Ad = sb + (uint32_t)buf * 32768u;
        uint32_t Bd = Ad + 16384u;
#pragma unroll
        for (int j = 0; j < 4; j++) {
            int idx = tid + j * 256;
            uint32_t sz = (row0 + (idx >> 3) < g.M) ? 16u : 0u;
            asm volatile("cp.async.cg.shared.global [%0], [%1], 16, %2;"
                         :: "r"(Ad + idx * 16), "l"(Asrc + (long)idx * 16), "r"(sz));
        }
#pragma unroll
        for (int j = 0; j < 4; j++) {
            int idx = tid + j * 256;
            asm volatile("cp.async.cg.shared.global [%0], [%1], 16;"
                         :: "r"(Bd + idx * 16), "l"(Bsrc + (long)idx * 16));
        }
        asm volatile("cp.async.commit_group;" ::: "memory");
    };

    issue(0);
    issue(1);
    issue(2);

    for (int t = 0; t < C; t++) {
        int rem = C - t;
        if (rem > 2)       asm volatile("cp.async.wait_group 2;" ::: "memory");
        else if (rem == 2) asm volatile("cp.async.wait_group 1;" ::: "memory");
        else               asm volatile("cp.async.wait_group 0;" ::: "memory");
        __syncthreads();
        uint32_t Ab = sb + (uint32_t)(t % 3) * 32768u;
        uint32_t Bb = Ab + 16384u;
#pragma unroll
        for (int kk = 0; kk < 4; kk++) {
            uint32_t a[2][4];
#pragma unroll
            for (int mi = 0; mi < 2; mi++) {
                int rr = wm * 32 + mi * 16 + (lane & 15);
                int byt = kk * 32 + ((lane >> 4) << 4);
                uint32_t ad = Ab + SWZ((uint32_t)(rr * 128 + byt));
                asm volatile("ldmatrix.sync.aligned.m8n8.x4.shared.b16 {%0,%1,%2,%3}, [%4];"
                    : "=r"(a[mi][0]), "=r"(a[mi][1]), "=r"(a[mi][2]), "=r"(a[mi][3])
                    : "r"(ad));
            }
            uint32_t b[8][2];
#pragma unroll
            for (int nj = 0; nj < 4; nj++) {
                int nn = wn * 64 + nj * 16 + ((lane >> 4) << 3) + (lane & 7);
                int byt = kk * 32 + (((lane >> 3) & 1) << 4);
                uint32_t bd2 = Bb + SWZ((uint32_t)(nn * 128 + byt));
                asm volatile("ldmatrix.sync.aligned.m8n8.x4.shared.b16 {%0,%1,%2,%3}, [%4];"
                    : "=r"(b[nj * 2][0]), "=r"(b[nj * 2][1]),
                      "=r"(b[nj * 2 + 1][0]), "=r"(b[nj * 2 + 1][1])
                    : "r"(bd2));
            }
#pragma unroll
            for (int mi = 0; mi < 2; mi++)
#pragma unroll
                for (int ni = 0; ni < 8; ni++) {
                    asm volatile(
                        "mma.sync.aligned.m16n8k16.row.col.f32.f16.f16.f32 "
                        "{%0,%1,%2,%3}, {%4,%5,%6,%7}, {%8,%9}, {%0,%1,%2,%3};"
                        : "+f"(acc[mi][ni][0]), "+f"(acc[mi][ni][1]),
                          "+f"(acc[mi][ni][2]), "+f"(acc[mi][ni][3])
                        : "r"(a[mi][0]), "r"(a[mi][1]), "r"(a[mi][2]), "r"(a[mi][3]),
                          "r"(b[ni][0]), "r"(b[ni][1]));
                }
        }
        __syncthreads();
        if (t + 3 < C) issue(t + 3);
    }

    int lr = lane >> 2, lc = (lane & 3) * 2;
#pragma unroll
    for (int mi = 0; mi < 2; mi++)
#pragma unroll
        for (int half = 0; half < 2; half++) {
            int row = row0 + wm * 32 + mi * 16 + half * 8 + lr;
            if (row < g.M) {
#pragma unroll
                for (int ni = 0; ni < 8; ni++) {
                    int c = col0 + wn * 64 + ni * 8 + lc;
                    epi_pair(g, row, c, acc[mi][ni][half * 2], acc[mi][ni][half * 2 + 1]);
                }
            }
        }
}

// ---------------------------------------------------------------------------
extern "C" void kernel_launch(void* const* d_in, const int* in_sizes, int n_in,
                              void* d_out, int out_size) {
    const float* x_user = (const float*)d_in[0];
    const float* x_news = (const float*)d_in[1];
    const float* h_user = (const float*)d_in[2];
    const float* h_news = (const float*)d_in[3];
    const float* Wl     = (const float*)d_in[4];
    const float* Wr     = (const float*)d_in[5];
    const float* bb     = (const float*)d_in[6];
    const int* src_un   = (const int*)d_in[7];
    const int* dst_un   = (const int*)d_in[8];
    const int* src_nu   = (const int*)d_in[9];
    const int* dst_nu   = (const int*)d_in[10];

    int NU = in_sizes[0] / D;
    int NN = in_sizes[1] / D;
    int E1 = in_sizes[7];
    int E2 = in_sizes[9];

    float* base = nullptr;
    int* deg = nullptr;
    cudaGetSymbolAddress((void**)&base, g_buf);
    cudaGetSymbolAddress((void**)&deg, g_deg);

    float* Axn = base + 0 * SZF;
    float* Ahn = base + 1 * SZF;
    float* Axu = base + 2 * SZF;
    float* Ahu = base + 3 * SZF;
    float* Acn = base + 4 * SZF;
    float* Acu = base + 5 * SZF;
    float* Zn  = base + 6 * SZF;
    float* Zu  = base + 7 * SZF;
    float* CXn = base + 8 * SZF;
    float* CXu = base + 9 * SZF;
    auto packP = [&](int idx) -> char* { return (char*)(base + (10L + idx) * SZF); };

    float* wf = base + 22 * SZF;
    char* WzrN = (char*)(wf);
    char* WzrU = (char*)(wf + 131072);
    char* WcxN = (char*)(wf + 262144);
    char* WcxU = (char*)(wf + 262144 + 32768);
    char* WchN = (char*)(wf + 262144 + 2 * 32768);
    char* WchU = (char*)(wf + 262144 + 3 * 32768);
    float* bzr_n = wf + 262144 + 4 * 32768;
    float* bzr_u = bzr_n + 256;
    float* bcx_n = bzr_u + 256;
    float* bcx_u = bcx_n + 128;
    float* bch_n = bcx_u + 128;
    float* bch_u = bch_n + 128;

    int* deg_n = deg;
    int* deg_u = deg + MAXN;

    float* out_u = (float*)d_out;
    float* out_n = (float*)d_out + (long)NU * D;

    long MbU = (long)NU * 128, MbN = (long)NN * 128;

    cudaFuncSetAttribute(gemm_mma, cudaFuncAttributeMaxDynamicSharedMemorySize, 98304);

    cudaStream_t s1;
    cudaStreamCreateWithFlags(&s1, cudaStreamNonBlocking);
    cudaEvent_t evPre, evHRn, evHRu, evJoin;
    cudaEventCreateWithFlags(&evPre, cudaEventDisableTiming);
    cudaEventCreateWithFlags(&evHRn, cudaEventDisableTiming);
    cudaEventCreateWithFlags(&evHRu, cudaEventDisableTiming);
    cudaEventCreateWithFlags(&evJoin, cudaEventDisableTiming);

    long t1 = (long)E1 * 32, t2 = (long)E2 * 32;

    // ---- shared preamble on default stream (S0): zero Ax/Ah + degrees ----
    zero_kernel<<<2048, 256>>>((float4*)base, (4 * SZF) / 4, deg, 2 * MAXN);
    build_bias<<<1, 128>>>(bb, bzr_n, bzr_u, bcx_n, bcx_u, bch_n, bch_u);
    cudaEventRecord(evPre, 0);
    cudaStreamWaitEvent(s1, evPre, 0);

    // S1: zero Ac buffers (needed only before agg1, overlaps S0 packs)
    zero_kernel<<<1024, 256, 0, s1>>>((float4*)(base + 4 * SZF), (2 * SZF) / 4, deg, 0);

    // ---- S0: news chain ----
    pack_w_zr<<<512, 256>>>(Wl, Wr, WzrN, 0);
    pack_w2<<<128, 256>>>(Wl, Wr, WcxN, 4, 0);
    pack_w2<<<128, 256>>>(Wl, Wr, WchN, 5, 0);
    pack_kernel<<<(NN * 32 + 255) / 256, 256>>>(x_news, nullptr, NN, packP(1));
    pack_kernel<<<(NN * 32 + 255) / 256, 256>>>(h_news, nullptr, NN, packP(3));
    agg2_kernel<<<(int)((t1 + 255) / 256), 256>>>(x_user, h_user, src_un, dst_un, E1,
                                                  Axn, Ahn, deg_n);
    pack_kernel<<<(NN * 32 + 255) / 256, 256>>>(Axn, deg_n, NN, packP(4));
    pack_kernel<<<(NN * 32 + 255) / 256, 256>>>(Ahn, deg_n, NN, packP(5));

    // ---- S1: user chain ----
    pack_w_zr<<<512, 256, 0, s1>>>(Wl, Wr, WzrU, 1);
    pack_w2<<<128, 256, 0, s1>>>(Wl, Wr, WcxU, 4, 1);
    pack_w2<<<128, 256, 0, s1>>>(Wl, Wr, WchU, 5, 1);
    pack_kernel<<<(NU * 32 + 255) / 256, 256, 0, s1>>>(x_user, nullptr, NU, packP(0));
    pack_kernel<<<(NU * 32 + 255) / 256, 256, 0, s1>>>(h_user, nullptr, NU, packP(2));
    agg2_kernel<<<(int)((t2 + 255) / 256), 256, 0, s1>>>(x_news, h_news, src_nu, dst_nu, E2,
                                                         Axu, Ahu, deg_u);
    pack_kernel<<<(NU * 32 + 255) / 256, 256, 0, s1>>>(Axu, deg_u, NU, packP(6));
    pack_kernel<<<(NU * 32 + 255) / 256, 256, 0, s1>>>(Ahu, deg_u, NU, packP(7));

    // ---- zr GEMMs (N=256): sigmoid + h*r repack epilogue ----
    {
        GP g{};
        g.hi[0] = packP(4); g.hi[1] = packP(1); g.hi[2] = packP(5); g.hi[3] = packP(3);
        for (int p = 0; p < 4; p++) g.lo[p] = g.hi[p] + 2 * MbN;
        g.B = WzrN; g.bias = bzr_n; g.H = h_news; g.out0 = Zn; g.outHR = packP(10);
        g.Mb = MbN; g.M = NN; g.N = 256; g.nparts = 4; g.mode = 0;
        gemm_mma<<<dim3((NN + 127) / 128, 2), 256, 98304>>>(g);
        cudaEventRecord(evHRn, 0);
    }
    {
        GP g{};
        g.hi[0] = packP(6); g.hi[1] = packP(0); g.hi[2] = packP(7); g.hi[3] = packP(2);
        for (int p = 0; p < 4; p++) g.lo[p] = g.hi[p] + 2 * MbU;
        g.B = WzrU; g.bias = bzr_u; g.H = h_user; g.out0 = Zu; g.outHR = packP(11);
        g.Mb = MbU; g.M = NU; g.N = 256; g.nparts = 4; g.mode = 0;
        gemm_mma<<<dim3((NU + 127) / 128, 2), 256, 98304, s1>>>(g);
        cudaEventRecord(evHRu, s1);
    }

    // ---- cx GEMMs (N=128) ----
    {
        GP g{};
        g.hi[0] = packP(4); g.hi[1] = packP(1);
        g.lo[0] = g.hi[0] + 2 * MbN; g.lo[1] = g.hi[1] + 2 * MbN;
        g.B = WcxN; g.bias = bcx_n; g.out0 = CXn;
        g.Mb = MbN; g.M = NN; g.N = 128; g.nparts = 2; g.mode = 1;
        gemm_mma<<<dim3((NN + 127) / 128, 1), 256, 98304>>>(g);
    }
    {
        GP g{};
        g.hi[0] = packP(6); g.hi[1] = packP(0);
        g.lo[0] = g.hi[0] + 2 * MbU; g.lo[1] = g.hi[1] + 2 * MbU;
        g.B = WcxU; g.bias = bcx_u; g.out0 = CXu;
        g.Mb = MbU; g.M = NU; g.N = 128; g.nparts = 2; g.mode = 1;
        gemm_mma<<<dim3((NU + 127) / 128, 1), 256, 98304, s1>>>(g);
    }

    // ---- h*r aggregation (cross dependency) ----
    cudaStreamWaitEvent(0, evHRu, 0);
    agg1_packed<<<(int)((t1 + 255) / 256), 256>>>(packP(11), MbU, src_un, dst_un, E1, Acn);
    pack_kernel<<<(NN * 32 + 255) / 256, 256>>>(Acn, deg_n, NN, packP(8));

    cudaStreamWaitEvent(s1, evHRn, 0);
    agg1_packed<<<(int)((t2 + 255) / 256), 256, 0, s1>>>(packP(10), MbN, src_nu, dst_nu, E2, Acu);
    pack_kernel<<<(NU * 32 + 255) / 256, 256, 0, s1>>>(Acu, deg_u, NU, packP(9));

    // ---- ch GEMMs: tanh + GRU update fused into d_out ----
    {
        GP g{};
        g.hi[0] = packP(8); g.hi[1] = packP(10);
        g.lo[0] = g.hi[0] + 2 * MbN; g.lo[1] = g.hi[1] + 2 * MbN;
        g.B = WchN; g.bias = bch_n; g.H = h_news; g.Z = Zn; g.CX = CXn; g.out0 = out_n;
        g.Mb = MbN; g.M = NN; g.N = 128; g.nparts = 2; g.mode = 2;
        gemm_mma<<<dim3((NN + 127) / 128, 1), 256, 98304>>>(g);
    }
    {
        GP g{};
        g.hi[0] = packP(9); g.hi[1] = packP(11);
        g.lo[0] = g.hi[0] + 2 * MbU; g.lo[1] = g.hi[1] + 2 * MbU;
        g.B = WchU; g.bias = bch_u; g.H = h_user; g.Z = Zu; g.CX = CXu; g.out0 = out_u;
        g.Mb = MbU; g.M = NU; g.N = 128; g.nparts = 2; g.mode = 2;
        gemm_mma<<<dim3((NU + 127) / 128, 1), 256, 98304, s1>>>(g);
    }

    // ---- join ----
    cudaEventRecord(evJoin, s1);
    cudaStreamWaitEvent(0, evJoin, 0);
}

// round 8
// speedup vs baseline: 2.0694x; 1.0207x over previous
#include <cuda_runtime.h>
#include <cuda_fp16.h>
#include <math.h>
#include <stdint.h>

#define D 128
#define MAXN 50000
#define SZF (50000L * 128L)

// fp32: Axn Ahn Axu Ahu Acn Acu Zn Zu (8*SZF, +2 spare)
// packed fp16 hi/lo regions: 12*SZF ; weights+bias tail
__device__ float g_buf[22L * SZF + 2 * 131072 + 4 * 32768 + 1024];
__device__ int g_deg[2 * MAXN];

// ---------------- helpers ----------------
__device__ __forceinline__ uint32_t s2u(const void* p) {
    uint32_t a;
    asm("{ .reg .u64 t; cvta.to.shared.u64 t, %1; cvt.u32.u64 %0, t; }" : "=r"(a) : "l"(p));
    return a;
}
__device__ __host__ __forceinline__ uint32_t SWZ(uint32_t x) { return x ^ ((x >> 3) & 0x70); }

__device__ __forceinline__ float sigf(float x) { return 1.f / (1.f + expf(-x)); }

__device__ __forceinline__ void split4(float4 v, uint2& hu, uint2& lu) {
    __half2 h01 = __floats2half2_rn(v.x, v.y);
    __half2 h23 = __floats2half2_rn(v.z, v.w);
    float lx = v.x - __half2float(__low2half(h01));
    float ly = v.y - __half2float(__high2half(h01));
    float lz = v.z - __half2float(__low2half(h23));
    float lw = v.w - __half2float(__high2half(h23));
    __half2 l01 = __floats2half2_rn(lx, ly);
    __half2 l23 = __floats2half2_rn(lz, lw);
    hu.x = *reinterpret_cast<uint32_t*>(&h01);
    hu.y = *reinterpret_cast<uint32_t*>(&h23);
    lu.x = *reinterpret_cast<uint32_t*>(&l01);
    lu.y = *reinterpret_cast<uint32_t*>(&l23);
}

__device__ __forceinline__ void split2(float x, float y, uint32_t& hw, uint32_t& lw) {
    __half2 h = __floats2half2_rn(x, y);
    float rx = x - __half2float(__low2half(h));
    float ry = y - __half2float(__high2half(h));
    __half2 l = __floats2half2_rn(rx, ry);
    hw = *reinterpret_cast<uint32_t*>(&h);
    lw = *reinterpret_cast<uint32_t*>(&l);
}

// ---------------- simple kernels ----------------
__global__ void zero_kernel(float4* p, long n4, int* d, int nd) {
    long stride = (long)gridDim.x * blockDim.x;
    long i0 = blockIdx.x * (long)blockDim.x + threadIdx.x;
    for (long j = i0; j < n4; j += stride) p[j] = make_float4(0.f, 0.f, 0.f, 0.f);
    for (long j = i0; j < nd; j += stride) d[j] = 0;
}

// warp-per-edge scatter of x and h rows + degree bump (fused)
__global__ void agg2_kernel(const float* __restrict__ fx, const float* __restrict__ fh,
                            const int* __restrict__ src, const int* __restrict__ dst, int E,
                            float* __restrict__ Ax, float* __restrict__ Ah,
                            int* __restrict__ deg) {
    long gid = blockIdx.x * (long)blockDim.x + threadIdx.x;
    int e = (int)(gid >> 5);
    int lane = (int)(gid & 31);
    if (e >= E) return;
    int s = src[e], d = dst[e];
    float4 vx = *(const float4*)(fx + (long)s * D + lane * 4);
    float4 vh = *(const float4*)(fh + (long)s * D + lane * 4);
    atomicAdd((float4*)(Ax + (long)d * D + lane * 4), vx);
    atomicAdd((float4*)(Ah + (long)d * D + lane * 4), vh);
    if (lane == 0) atomicAdd(&deg[d], 1);
}

// gather packed hi/lo fp16 rows (reconstruct fp32), scatter-add
__global__ void agg1_packed(const char* __restrict__ P, long Mb,
                            const int* __restrict__ src, const int* __restrict__ dst, int E,
                            float* __restrict__ A) {
    long gid = blockIdx.x * (long)blockDim.x + threadIdx.x;
    int e = (int)(gid >> 5);
    int lane = (int)(gid & 31);
    if (e >= E) return;
    int s = src[e], d = dst[e];
    int c4 = lane * 4;
    int q = c4 >> 6;
    int inner = c4 & 63;
    uint32_t sw = SWZ((uint32_t)s * 128u + (uint32_t)inner * 2u);
    uint2 hu = *(const uint2*)(P + (long)q * Mb + sw);
    uint2 lu = *(const uint2*)(P + 2 * Mb + (long)q * Mb + sw);
    float2 a = __half22float2(*reinterpret_cast<__half2*>(&hu.x));
    float2 b = __half22float2(*reinterpret_cast<__half2*>(&hu.y));
    float2 c = __half22float2(*reinterpret_cast<__half2*>(&lu.x));
    float2 dd = __half22float2(*reinterpret_cast<__half2*>(&lu.y));
    float4 v = make_float4(a.x + c.x, a.y + c.y, b.x + dd.x, b.y + dd.y);
    atomicAdd((float4*)(A + (long)d * D + c4), v);
}

// fp32 [M,128] (* 1/deg optional) -> packed hi/lo fp16 SW128 chunks
__global__ void pack_kernel(const float* __restrict__ src, const int* __restrict__ deg,
                            int M, char* __restrict__ dst) {
    long i = blockIdx.x * (long)blockDim.x + threadIdx.x;
    if (i >= (long)M * 32) return;
    int row = (int)(i >> 5);
    int c4 = ((int)i & 31) * 4;
    float inv = 1.f;
    if (deg) inv = 1.f / (float)max(deg[row], 1);
    float4 v = ((const float4*)src)[i];
    v.x *= inv; v.y *= inv; v.z *= inv; v.w *= inv;
    uint2 hu, lu;
    split4(v, hu, lu);
    int q = c4 >> 6;
    int inner = c4 & 63;
    uint32_t sw = SWZ((uint32_t)row * 128u + (uint32_t)inner * 2u);
    long Mb = (long)M * 128;
    *(uint2*)(dst + (long)q * Mb + sw) = hu;
    *(uint2*)(dst + 2 * Mb + (long)q * Mb + sw) = lu;
}

// ---------------- weight packing (fp16) ----------------
__global__ void pack_w_zr(const float* __restrict__ Wl, const float* __restrict__ Wr,
                          char* __restrict__ dst, int t) {
    int j = blockIdx.x * blockDim.x + threadIdx.x;
    if (j >= 4 * 256 * 128) return;
    int k = j & 127;
    int n = (j >> 7) & 255;
    int p = j >> 15;
    int gz = (n < 128) ? 0 : 2;
    int cc = n & 127;
    int g = gz + (p >> 1);
    const float* S = (p & 1) ? Wr : Wl;
    float w = S[((long)(g * 2 + t) * 128 + k) * 128 + cc];
    __half h = __float2half_rn(w);
    int q = k >> 6;
    int inner = k & 63;
    uint32_t sw = SWZ((uint32_t)n * 128u + (uint32_t)inner * 2u);
    const int Nb = 256 * 128;
    *(unsigned short*)(dst + (size_t)(p * 2 + q) * Nb + sw) = *reinterpret_cast<unsigned short*>(&h);
}

// fused cx|ch weights: blocks ((pbase+p)*2+q), p in {0:Wl[g],1:Wr[g]}, N=128
__global__ void pack_w2(const float* __restrict__ Wl, const float* __restrict__ Wr,
                        char* __restrict__ dst, int g, int t, int pbase) {
    int j = blockIdx.x * blockDim.x + threadIdx.x;
    if (j >= 2 * 128 * 128) return;
    int k = j & 127;
    int n = (j >> 7) & 127;
    int p = j >> 14;
    const float* S = p ? Wr : Wl;
    float w = S[((long)(g * 2 + t) * 128 + k) * 128 + n];
    __half h = __float2half_rn(w);
    int q = k >> 6;
    int inner = k & 63;
    uint32_t sw = SWZ((uint32_t)n * 128u + (uint32_t)inner * 2u);
    const int Nb = 128 * 128;
    *(unsigned short*)(dst + (size_t)((pbase + p) * 2 + q) * Nb + sw) = *reinterpret_cast<unsigned short*>(&h);
}

__global__ void build_bias(const float* __restrict__ b,
                           float* bzr_n, float* bzr_u, float* bc_n, float* bc_u) {
    int c = threadIdx.x;
    if (c >= 128) return;
#define BB(g, t) b[((g) * 2 + (t)) * 128 + c]
    bzr_n[c]       = BB(0, 0) + BB(1, 0);
    bzr_n[128 + c] = BB(2, 0) + BB(3, 0);
    bzr_u[c]       = BB(0, 1) + BB(1, 1);
    bzr_u[128 + c] = BB(2, 1) + BB(3, 1);
    bc_n[c] = BB(4, 0) + BB(5, 0);
    bc_u[c] = BB(4, 1) + BB(5, 1);
#undef BB
}

// ---------------- HMMA GEMM (fp16 2-term, 3-stage cp.async) ----------------
struct GP {
    const char* hi[4];
    const char* lo[4];
    const char* B;
    const float* bias;
    const float* H;
    const float* Z;
    float* out0;
    char* outHR;
    long Mb;
    int M, N, nparts, mode;   // mode 0=zr, 2=ch(fused cx|ch)
};

__device__ __forceinline__ void epi_pair(const GP& g, int row, int c, float v0, float v1) {
    v0 += g.bias[c];
    v1 += g.bias[c + 1];
    long rb = (long)row * D;
    if (g.mode == 0) {
        if (c < 128) {
            g.out0[rb + c] = sigf(v0);
            g.out0[rb + c + 1] = sigf(v1);
        } else {
            int cc = c - 128;
            float r0 = sigf(v0) * g.H[rb + cc];
            float r1 = sigf(v1) * g.H[rb + cc + 1];
            uint32_t hw, lw;
            split2(r0, r1, hw, lw);
            uint32_t sw = SWZ((uint32_t)row * 128u + (uint32_t)(cc & 63) * 2u);
            int q = cc >> 6;
            *(uint32_t*)(g.outHR + (long)q * g.Mb + sw) = hw;
            *(uint32_t*)(g.outHR + 2 * g.Mb + (long)q * g.Mb + sw) = lw;
        }
    } else {
        float z0 = g.Z[rb + c], z1 = g.Z[rb + c + 1];
        float h0 = g.H[rb + c], h1 = g.H[rb + c + 1];
        float t0 = tanhf(v0);
        float t1 = tanhf(v1);
        g.out0[rb + c] = z0 * h0 + (1.f - z0) * t0;
        g.out0[rb + c + 1] = z1 * h1 + (1.f - z1) * t1;
    }
}

__global__ void __launch_bounds__(256) gemm_mma(GP g) {
    extern __shared__ char smem[];
    uint32_t sb = s2u(smem);
    int tid = threadIdx.x;
    int lane = tid & 31, wid = tid >> 5;
    int wm = wid & 3, wn = wid >> 2;          // 4x2 warp grid
    int row0 = blockIdx.x * 128;
    int col0 = blockIdx.y * 128;
    long Nb = (long)g.N * 128;
    int C = g.nparts * 4;                      // parts x 2 terms x 2 chunks

    float acc[2][8][4];
#pragma unroll
    for (int i = 0; i < 2; i++)
#pragma unroll
        for (int j = 0; j < 8; j++)
#pragma unroll
            for (int k = 0; k < 4; k++) acc[i][j][k] = 0.f;

    auto issue = [&](int t) {
        int buf = t % 3;
        int p = t >> 2, r = t & 3, term = r >> 1, q = r & 1;
        const char* Asrc = (term ? g.lo[p] : g.hi[p]) + (long)q * g.Mb + (long)row0 * 128;
        const char* Bsrc = g.B + (size_t)(p * 2 + q) * Nb + (long)col0 * 128;
        uint32_t Ad = sb + (uint32_t)buf * 32768u;
        uint32_t Bd = Ad + 16384u;
#pragma unroll
        for (int j = 0; j < 4; j++) {
            int idx = tid + j * 256;
            uint32_t sz = (row0 + (idx >> 3) < g.M) ? 16u : 0u;
            asm volatile("cp.async.cg.shared.global [%0], [%1], 16, %2;"
                         :: "r"(Ad + idx * 16), "l"(Asrc + (long)idx * 16), "r"(sz));
        }
#pragma unroll
        for (int j = 0; j < 4; j++) {
            int idx = tid + j * 256;
            asm volatile("cp.async.cg.shared.global [%0], [%1], 16;"
                         :: "r"(Bd + idx * 16), "l"(Bsrc + (long)idx * 16));
        }
        asm volatile("cp.async.commit_group;" ::: "memory");
    };

    issue(0);
    issue(1);
    issue(2);

    for (int t = 0; t < C; t++) {
        int rem = C - t;
        if (rem > 2)       asm volatile("cp.async.wait_group 2;" ::: "memory");
        else if (rem == 2) asm volatile("cp.async.wait_group 1;" ::: "memory");
        else               asm volatile("cp.async.wait_group 0;" ::: "memory");
        __syncthreads();
        uint32_t Ab = sb + (uint32_t)(t % 3) * 32768u;
        uint32_t Bb = Ab + 16384u;
#pragma unroll
        for (int kk = 0; kk < 4; kk++) {
            uint32_t a[2][4];
#pragma unroll
            for (int mi = 0; mi < 2; mi++) {
                int rr = wm * 32 + mi * 16 + (lane & 15);
                int byt = kk * 32 + ((lane >> 4) << 4);
                uint32_t ad = Ab + SWZ((uint32_t)(rr * 128 + byt));
                asm volatile("ldmatrix.sync.aligned.m8n8.x4.shared.b16 {%0,%1,%2,%3}, [%4];"
                    : "=r"(a[mi][0]), "=r"(a[mi][1]), "=r"(a[mi][2]), "=r"(a[mi][3])
                    : "r"(ad));
            }
            uint32_t b[8][2];
#pragma unroll
            for (int nj = 0; nj < 4; nj++) {
                int nn = wn * 64 + nj * 16 + ((lane >> 4) << 3) + (lane & 7);
                int byt = kk * 32 + (((lane >> 3) & 1) << 4);
                uint32_t bd2 = Bb + SWZ((uint32_t)(nn * 128 + byt));
                asm volatile("ldmatrix.sync.aligned.m8n8.x4.shared.b16 {%0,%1,%2,%3}, [%4];"
                    : "=r"(b[nj * 2][0]), "=r"(b[nj * 2][1]),
                      "=r"(b[nj * 2 + 1][0]), "=r"(b[nj * 2 + 1][1])
                    : "r"(bd2));
            }
#pragma unroll
            for (int mi = 0; mi < 2; mi++)
#pragma unroll
                for (int ni = 0; ni < 8; ni++) {
                    asm volatile(
                        "mma.sync.aligned.m16n8k16.row.col.f32.f16.f16.f32 "
                        "{%0,%1,%2,%3}, {%4,%5,%6,%7}, {%8,%9}, {%0,%1,%2,%3};"
                        : "+f"(acc[mi][ni][0]), "+f"(acc[mi][ni][1]),
                          "+f"(acc[mi][ni][2]), "+f"(acc[mi][ni][3])
                        : "r"(a[mi][0]), "r"(a[mi][1]), "r"(a[mi][2]), "r"(a[mi][3]),
                          "r"(b[ni][0]), "r"(b[ni][1]));
                }
        }
        __syncthreads();
        if (t + 3 < C) issue(t + 3);
    }

    int lr = lane >> 2, lc = (lane & 3) * 2;
#pragma unroll
    for (int mi = 0; mi < 2; mi++)
#pragma unroll
        for (int half = 0; half < 2; half++) {
            int row = row0 + wm * 32 + mi * 16 + half * 8 + lr;
            if (row < g.M) {
#pragma unroll
                for (int ni = 0; ni < 8; ni++) {
                    int c = col0 + wn * 64 + ni * 8 + lc;
                    epi_pair(g, row, c, acc[mi][ni][half * 2], acc[mi][ni][half * 2 + 1]);
                }
            }
        }
}

// ---------------------------------------------------------------------------
extern "C" void kernel_launch(void* const* d_in, const int* in_sizes, int n_in,
                              void* d_out, int out_size) {
    const float* x_user = (const float*)d_in[0];
    const float* x_news = (const float*)d_in[1];
    const float* h_user = (const float*)d_in[2];
    const float* h_news = (const float*)d_in[3];
    const float* Wl     = (const float*)d_in[4];
    const float* Wr     = (const float*)d_in[5];
    const float* bb     = (const float*)d_in[6];
    const int* src_un   = (const int*)d_in[7];
    const int* dst_un   = (const int*)d_in[8];
    const int* src_nu   = (const int*)d_in[9];
    const int* dst_nu   = (const int*)d_in[10];

    int NU = in_sizes[0] / D;
    int NN = in_sizes[1] / D;
    int E1 = in_sizes[7];
    int E2 = in_sizes[9];

    float* base = nullptr;
    int* deg = nullptr;
    cudaGetSymbolAddress((void**)&base, g_buf);
    cudaGetSymbolAddress((void**)&deg, g_deg);

    float* Axn = base + 0 * SZF;
    float* Ahn = base + 1 * SZF;
    float* Axu = base + 2 * SZF;
    float* Ahu = base + 3 * SZF;
    float* Acn = base + 4 * SZF;
    float* Acu = base + 5 * SZF;
    float* Zn  = base + 6 * SZF;
    float* Zu  = base + 7 * SZF;
    // packed: 0 PXU, 1 PXN, 2 PHU, 3 PHN, 4 PAXN, 5 PAHN, 6 PAXU, 7 PAHU,
    //         8 PACN, 9 PACU, 10 PHRN, 11 PHRU
    auto packP = [&](int idx) -> char* { return (char*)(base + (10L + idx) * SZF); };

    float* wf = base + 22 * SZF;
    char* WzrN = (char*)(wf);
    char* WzrU = (char*)(wf + 131072);
    char* WcN  = (char*)(wf + 262144);
    char* WcU  = (char*)(wf + 262144 + 32768);
    float* bzr_n = wf + 262144 + 4 * 32768;
    float* bzr_u = bzr_n + 256;
    float* bc_n  = bzr_u + 256;
    float* bc_u  = bc_n + 128;

    int* deg_n = deg;
    int* deg_u = deg + MAXN;

    float* out_u = (float*)d_out;
    float* out_n = (float*)d_out + (long)NU * D;

    long MbU = (long)NU * 128, MbN = (long)NN * 128;

    cudaFuncSetAttribute(gemm_mma, cudaFuncAttributeMaxDynamicSharedMemorySize, 98304);

    cudaStream_t s1;
    cudaStreamCreateWithFlags(&s1, cudaStreamNonBlocking);
    cudaEvent_t evFork, evStag, evPacksZero, evDegU, evHRu, evAcu, evJoin;
    cudaEventCreateWithFlags(&evFork, cudaEventDisableTiming);
    cudaEventCreateWithFlags(&evStag, cudaEventDisableTiming);
    cudaEventCreateWithFlags(&evPacksZero, cudaEventDisableTiming);
    cudaEventCreateWithFlags(&evDegU, cudaEventDisableTiming);
    cudaEventCreateWithFlags(&evHRu, cudaEventDisableTiming);
    cudaEventCreateWithFlags(&evAcu, cudaEventDisableTiming);
    cudaEventCreateWithFlags(&evJoin, cudaEventDisableTiming);

    long t1 = (long)E1 * 32, t2 = (long)E2 * 32;

    // ===== capture fork: s1 joins via event from the origin stream =====
    cudaEventRecord(evFork, 0);
    cudaStreamWaitEvent(s1, evFork, 0);

    // ===== S0: zero main accumulators + degrees, news-direction agg =====
    zero_kernel<<<2048, 256>>>((float4*)base, (4 * SZF) / 4, deg, 2 * MAXN);
    agg2_kernel<<<(int)((t1 + 255) / 256), 256>>>(x_user, h_user, src_un, dst_un, E1,
                                                  Axn, Ahn, deg_n);
    pack_kernel<<<(NN * 32 + 255) / 256, 256>>>(Axn, deg_n, NN, packP(4));
    pack_kernel<<<(NN * 32 + 255) / 256, 256>>>(Ahn, deg_n, NN, packP(5));
    cudaEventRecord(evStag, 0);   // S1 may start its agg2 now (zero done; staggered)

    // ===== S1: all packs + zero Ac (overlaps S0's zero + agg2_E1) =====
    pack_w_zr<<<512, 256, 0, s1>>>(Wl, Wr, WzrN, 0);
    pack_w_zr<<<512, 256, 0, s1>>>(Wl, Wr, WzrU, 1);
    pack_w2<<<128, 256, 0, s1>>>(Wl, Wr, WcN, 4, 0, 0);
    pack_w2<<<128, 256, 0, s1>>>(Wl, Wr, WcN, 5, 0, 2);
    pack_w2<<<128, 256, 0, s1>>>(Wl, Wr, WcU, 4, 1, 0);
    pack_w2<<<128, 256, 0, s1>>>(Wl, Wr, WcU, 5, 1, 2);
    build_bias<<<1, 128, 0, s1>>>(bb, bzr_n, bzr_u, bc_n, bc_u);
    pack_kernel<<<(NU * 32 + 255) / 256, 256, 0, s1>>>(x_user, nullptr, NU, packP(0));
    pack_kernel<<<(NN * 32 + 255) / 256, 256, 0, s1>>>(x_news, nullptr, NN, packP(1));
    pack_kernel<<<(NU * 32 + 255) / 256, 256, 0, s1>>>(h_user, nullptr, NU, packP(2));
    pack_kernel<<<(NN * 32 + 255) / 256, 256, 0, s1>>>(h_news, nullptr, NN, packP(3));
    zero_kernel<<<1024, 256, 0, s1>>>((float4*)(base + 4 * SZF), (2 * SZF) / 4, deg, 0);
    cudaEventRecord(evPacksZero, s1);

    // ===== S0: zr GEMM news (needs S1 packs + Ac zero) =====
    cudaStreamWaitEvent(0, evPacksZero, 0);
    {
        GP g{};
        g.hi[0] = packP(4); g.hi[1] = packP(1); g.hi[2] = packP(5); g.hi[3] = packP(3);
        for (int p = 0; p < 4; p++) g.lo[p] = g.hi[p] + 2 * MbN;
        g.B = WzrN; g.bias = bzr_n; g.H = h_news; g.out0 = Zn; g.outHR = packP(10);
        g.Mb = MbN; g.M = NN; g.N = 256; g.nparts = 4; g.mode = 0;
        gemm_mma<<<dim3((NN + 127) / 128, 2), 256, 98304>>>(g);
    }
    // S0: agg1 over HRn -> Acu (overlaps S1's zrU)
    agg1_packed<<<(int)((t2 + 255) / 256), 256>>>(packP(10), MbN, src_nu, dst_nu, E2, Acu);
    cudaStreamWaitEvent(0, evDegU, 0);   // deg_u produced by S1's agg2_E2
    pack_kernel<<<(NU * 32 + 255) / 256, 256>>>(Acu, deg_u, NU, packP(9));
    cudaEventRecord(evAcu, 0);

    // ===== S1: user-direction agg (staggered vs S0's zrN) + zr GEMM =====
    cudaStreamWaitEvent(s1, evStag, 0);
    agg2_kernel<<<(int)((t2 + 255) / 256), 256, 0, s1>>>(x_news, h_news, src_nu, dst_nu, E2,
                                                         Axu, Ahu, deg_u);
    cudaEventRecord(evDegU, s1);
    pack_kernel<<<(NU * 32 + 255) / 256, 256, 0, s1>>>(Axu, deg_u, NU, packP(6));
    pack_kernel<<<(NU * 32 + 255) / 256, 256, 0, s1>>>(Ahu, deg_u, NU, packP(7));
    {
        GP g{};
        g.hi[0] = packP(6); g.hi[1] = packP(0); g.hi[2] = packP(7); g.hi[3] = packP(2);
        for (int p = 0; p < 4; p++) g.lo[p] = g.hi[p] + 2 * MbU;
        g.B = WzrU; g.bias = bzr_u; g.H = h_user; g.out0 = Zu; g.outHR = packP(11);
        g.Mb = MbU; g.M = NU; g.N = 256; g.nparts = 4; g.mode = 0;
        gemm_mma<<<dim3((NU + 127) / 128, 2), 256, 98304, s1>>>(g);
    }
    cudaEventRecord(evHRu, s1);

    // S1: fused cx|ch GEMM user -> out_u (needs Acu pack from S0)
    cudaStreamWaitEvent(s1, evAcu, 0);
    {
        GP g{};
        g.hi[0] = packP(6); g.hi[1] = packP(0); g.hi[2] = packP(9); g.hi[3] = packP(11);
        for (int p = 0; p < 4; p++) g.lo[p] = g.hi[p] + 2 * MbU;
        g.B = WcU; g.bias = bc_u; g.H = h_user; g.Z = Zu; g.out0 = out_u;
        g.Mb = MbU; g.M = NU; g.N = 128; g.nparts = 4; g.mode = 2;
        gemm_mma<<<dim3((NU + 127) / 128, 1), 256, 98304, s1>>>(g);
    }
    cudaEventRecord(evJoin, s1);

    // ===== S0: agg1 over HRu -> Acn, then fused ch news -> out_n =====
    cudaStreamWaitEvent(0, evHRu, 0);
    agg1_packed<<<(int)((t1 + 255) / 256), 256>>>(packP(11), MbU, src_un, dst_un, E1, Acn);
    pack_kernel<<<(NN * 32 + 255) / 256, 256>>>(Acn, deg_n, NN, packP(8));
    {
        GP g{};
        g.hi[0] = packP(4); g.hi[1] = packP(1); g.hi[2] = packP(8); g.hi[3] = packP(10);
        for (int p = 0; p < 4; p++) g.lo[p] = g.hi[p] + 2 * MbN;
        g.B = WcN; g.bias = bc_n; g.H = h_news; g.Z = Zn; g.out0 = out_n;
        g.Mb = MbN; g.M = NN; g.N = 128; g.nparts = 4; g.mode = 2;
        gemm_mma<<<dim3((NN + 127) / 128, 1), 256, 98304>>>(g);
    }

    // ===== join =====
    cudaStreamWaitEvent(0, evJoin, 0);
}

// round 9
// speedup vs baseline: 3.3647x; 1.6260x over previous
#include <cuda_runtime.h>
#include <cuda_fp16.h>
#include <math.h>
#include <stdint.h>

#define D 128
#define MAXN 50000
#define MAXE 1000000
#define SZF (50000L * 128L)

// regions 6,7: Zn, Zu fp32. packed fp16 hi/lo regions at 10.. ; weights tail
__device__ float g_buf[22L * SZF + 2 * 131072 + 4 * 32768 + 1024];
__device__ int g_deg[2 * MAXN];
// sorted src indices + offsets + cursors
__device__ int g_idx[2 * MAXE + 2 * (MAXN + 8) + 2 * MAXN];

// ---------------- helpers ----------------
__device__ __forceinline__ uint32_t s2u(const void* p) {
    uint32_t a;
    asm("{ .reg .u64 t; cvta.to.shared.u64 t, %1; cvt.u32.u64 %0, t; }" : "=r"(a) : "l"(p));
    return a;
}
__device__ __host__ __forceinline__ uint32_t SWZ(uint32_t x) { return x ^ ((x >> 3) & 0x70); }

__device__ __forceinline__ float sigf(float x) { return 1.f / (1.f + expf(-x)); }

__device__ __forceinline__ void split4(float4 v, uint2& hu, uint2& lu) {
    __half2 h01 = __floats2half2_rn(v.x, v.y);
    __half2 h23 = __floats2half2_rn(v.z, v.w);
    float lx = v.x - __half2float(__low2half(h01));
    float ly = v.y - __half2float(__high2half(h01));
    float lz = v.z - __half2float(__low2half(h23));
    float lw = v.w - __half2float(__high2half(h23));
    __half2 l01 = __floats2half2_rn(lx, ly);
    __half2 l23 = __floats2half2_rn(lz, lw);
    hu.x = *reinterpret_cast<uint32_t*>(&h01);
    hu.y = *reinterpret_cast<uint32_t*>(&h23);
    lu.x = *reinterpret_cast<uint32_t*>(&l01);
    lu.y = *reinterpret_cast<uint32_t*>(&l23);
}

__device__ __forceinline__ void split2(float x, float y, uint32_t& hw, uint32_t& lw) {
    __half2 h = __floats2half2_rn(x, y);
    float rx = x - __half2float(__low2half(h));
    float ry = y - __half2float(__high2half(h));
    __half2 l = __floats2half2_rn(rx, ry);
    hw = *reinterpret_cast<uint32_t*>(&h);
    lw = *reinterpret_cast<uint32_t*>(&l);
}

// ---------------- sort-by-destination machinery ----------------
__global__ void zero_int(int* p, int n) {
    int i = blockIdx.x * blockDim.x + threadIdx.x;
    if (i < n) p[i] = 0;
}

__global__ void count_deg(const int* __restrict__ dst, int E, int* __restrict__ deg) {
    int i = blockIdx.x * blockDim.x + threadIdx.x;
    if (i < E) atomicAdd(&deg[dst[i]], 1);
}

// single-block exclusive scan: off[0..n], cur[i] = off[i]
__global__ void scan_kernel(const int* __restrict__ deg, int n,
                            int* __restrict__ off, int* __restrict__ cur) {
    __shared__ int wsum[32];
    __shared__ int carry;
    int tid = threadIdx.x, lane = tid & 31, w = tid >> 5;
    if (tid == 0) { carry = 0; off[0] = 0; }
    __syncthreads();
    for (int base = 0; base < n; base += 1024) {
        int i = base + tid;
        int v = (i < n) ? deg[i] : 0;
        int x = v;
#pragma unroll
        for (int o = 1; o < 32; o <<= 1) {
            int y = __shfl_up_sync(0xFFFFFFFFu, x, o);
            if (lane >= o) x += y;
        }
        if (lane == 31) wsum[w] = x;
        __syncthreads();
        if (w == 0) {
            int s = wsum[lane];
#pragma unroll
            for (int o = 1; o < 32; o <<= 1) {
                int y = __shfl_up_sync(0xFFFFFFFFu, s, o);
                if (lane >= o) s += y;
            }
            wsum[lane] = s;
        }
        __syncthreads();
        int incl = x + (w ? wsum[w - 1] : 0) + carry;
        if (i < n) { off[i + 1] = incl; cur[i] = incl - v; }
        __syncthreads();
        if (tid == 1023) carry = incl;
        __syncthreads();
    }
}

__global__ void scatter_kernel(const int* __restrict__ src, const int* __restrict__ dst,
                               int E, int* __restrict__ cur, int* __restrict__ ssrc) {
    int i = blockIdx.x * blockDim.x + threadIdx.x;
    if (i < E) {
        int pos = atomicAdd(&cur[dst[i]], 1);
        ssrc[pos] = src[i];
    }
}

// ---------------- pull-mode aggregation (warp per dst node) ----------------
// mean of fx,fh source rows -> packed hi/lo fp16 SW128 chunks, no atomics
__global__ void gather2_pack(const float* __restrict__ fx, const float* __restrict__ fh,
                             const int* __restrict__ off, const int* __restrict__ ssrc,
                             int n, char* __restrict__ Px, char* __restrict__ Ph, long Mb) {
    long gid = blockIdx.x * (long)blockDim.x + threadIdx.x;
    int node = (int)(gid >> 5), lane = (int)(gid & 31);
    if (node >= n) return;
    int s0 = off[node], s1 = off[node + 1];
    int c4 = lane * 4;
    float4 sx = make_float4(0.f, 0.f, 0.f, 0.f);
    float4 sh = make_float4(0.f, 0.f, 0.f, 0.f);
    int i = s0;
    for (; i + 1 < s1; i += 2) {
        int a = ssrc[i], b = ssrc[i + 1];
        float4 xa = *(const float4*)(fx + (long)a * D + c4);
        float4 xb = *(const float4*)(fx + (long)b * D + c4);
        float4 ha = *(const float4*)(fh + (long)a * D + c4);
        float4 hb = *(const float4*)(fh + (long)b * D + c4);
        sx.x += xa.x + xb.x; sx.y += xa.y + xb.y; sx.z += xa.z + xb.z; sx.w += xa.w + xb.w;
        sh.x += ha.x + hb.x; sh.y += ha.y + hb.y; sh.z += ha.z + hb.z; sh.w += ha.w + hb.w;
    }
    if (i < s1) {
        int a = ssrc[i];
        float4 xa = *(const float4*)(fx + (long)a * D + c4);
        float4 ha = *(const float4*)(fh + (long)a * D + c4);
        sx.x += xa.x; sx.y += xa.y; sx.z += xa.z; sx.w += xa.w;
        sh.x += ha.x; sh.y += ha.y; sh.z += ha.z; sh.w += ha.w;
    }
    float inv = 1.f / (float)max(s1 - s0, 1);
    sx.x *= inv; sx.y *= inv; sx.z *= inv; sx.w *= inv;
    sh.x *= inv; sh.y *= inv; sh.z *= inv; sh.w *= inv;
    int q = c4 >> 6;
    int inner = c4 & 63;
    uint32_t sw = SWZ((uint32_t)node * 128u + (uint32_t)inner * 2u);
    uint2 hu, lu;
    split4(sx, hu, lu);
    *(uint2*)(Px + (long)q * Mb + sw) = hu;
    *(uint2*)(Px + 2 * Mb + (long)q * Mb + sw) = lu;
    split4(sh, hu, lu);
    *(uint2*)(Ph + (long)q * Mb + sw) = hu;
    *(uint2*)(Ph + 2 * Mb + (long)q * Mb + sw) = lu;
}

// mean of packed hi/lo source rows -> packed hi/lo output, no atomics
__global__ void gather1_pack(const char* __restrict__ P, long MbP,
                             const int* __restrict__ off, const int* __restrict__ ssrc,
                             int n, char* __restrict__ dstP, long MbD) {
    long gid = blockIdx.x * (long)blockDim.x + threadIdx.x;
    int node = (int)(gid >> 5), lane = (int)(gid & 31);
    if (node >= n) return;
    int s0 = off[node], s1 = off[node + 1];
    int c4 = lane * 4;
    int q = c4 >> 6;
    int inner = c4 & 63;
    float4 acc = make_float4(0.f, 0.f, 0.f, 0.f);
    for (int i = s0; i < s1; i++) {
        int s = ssrc[i];
        uint32_t sw = SWZ((uint32_t)s * 128u + (uint32_t)inner * 2u);
        uint2 hu = *(const uint2*)(P + (long)q * MbP + sw);
        uint2 lu = *(const uint2*)(P + 2 * MbP + (long)q * MbP + sw);
        float2 a = __half22float2(*reinterpret_cast<__half2*>(&hu.x));
        float2 b = __half22float2(*reinterpret_cast<__half2*>(&hu.y));
        float2 c = __half22float2(*reinterpret_cast<__half2*>(&lu.x));
        float2 d = __half22float2(*reinterpret_cast<__half2*>(&lu.y));
        acc.x += a.x + c.x; acc.y += a.y + c.y; acc.z += b.x + d.x; acc.w += b.y + d.y;
    }
    float inv = 1.f / (float)max(s1 - s0, 1);
    acc.x *= inv; acc.y *= inv; acc.z *= inv; acc.w *= inv;
    uint2 hu, lu;
    split4(acc, hu, lu);
    uint32_t swd = SWZ((uint32_t)node * 128u + (uint32_t)inner * 2u);
    *(uint2*)(dstP + (long)q * MbD + swd) = hu;
    *(uint2*)(dstP + 2 * MbD + (long)q * MbD + swd) = lu;
}

// fp32 [M,128] -> packed hi/lo fp16 SW128 (inputs only)
__global__ void pack_kernel(const float* __restrict__ src, int M, char* __restrict__ dst) {
    long i = blockIdx.x * (long)blockDim.x + threadIdx.x;
    if (i >= (long)M * 32) return;
    int row = (int)(i >> 5);
    int c4 = ((int)i & 31) * 4;
    float4 v = ((const float4*)src)[i];
    uint2 hu, lu;
    split4(v, hu, lu);
    int q = c4 >> 6;
    int inner = c4 & 63;
    uint32_t sw = SWZ((uint32_t)row * 128u + (uint32_t)inner * 2u);
    long Mb = (long)M * 128;
    *(uint2*)(dst + (long)q * Mb + sw) = hu;
    *(uint2*)(dst + 2 * Mb + (long)q * Mb + sw) = lu;
}

// ---------------- weight packing (fp16) ----------------
__global__ void pack_w_zr(const float* __restrict__ Wl, const float* __restrict__ Wr,
                          char* __restrict__ dst, int t) {
    int j = blockIdx.x * blockDim.x + threadIdx.x;
    if (j >= 4 * 256 * 128) return;
    int k = j & 127;
    int n = (j >> 7) & 255;
    int p = j >> 15;
    int gz = (n < 128) ? 0 : 2;
    int cc = n & 127;
    int g = gz + (p >> 1);
    const float* S = (p & 1) ? Wr : Wl;
    float w = S[((long)(g * 2 + t) * 128 + k) * 128 + cc];
    __half h = __float2half_rn(w);
    int q = k >> 6;
    int inner = k & 63;
    uint32_t sw = SWZ((uint32_t)n * 128u + (uint32_t)inner * 2u);
    const int Nb = 256 * 128;
    *(unsigned short*)(dst + (size_t)(p * 2 + q) * Nb + sw) = *reinterpret_cast<unsigned short*>(&h);
}

__global__ void pack_w2(const float* __restrict__ Wl, const float* __restrict__ Wr,
                        char* __restrict__ dst, int g, int t, int pbase) {
    int j = blockIdx.x * blockDim.x + threadIdx.x;
    if (j >= 2 * 128 * 128) return;
    int k = j & 127;
    int n = (j >> 7) & 127;
    int p = j >> 14;
    const float* S = p ? Wr : Wl;
    float w = S[((long)(g * 2 + t) * 128 + k) * 128 + n];
    __half h = __float2half_rn(w);
    int q = k >> 6;
    int inner = k & 63;
    uint32_t sw = SWZ((uint32_t)n * 128u + (uint32_t)inner * 2u);
    const int Nb = 128 * 128;
    *(unsigned short*)(dst + (size_t)((pbase + p) * 2 + q) * Nb + sw) = *reinterpret_cast<unsigned short*>(&h);
}

__global__ void build_bias(const float* __restrict__ b,
                           float* bzr_n, float* bzr_u, float* bc_n, float* bc_u) {
    int c = threadIdx.x;
    if (c >= 128) return;
#define BB(g, t) b[((g) * 2 + (t)) * 128 + c]
    bzr_n[c]       = BB(0, 0) + BB(1, 0);
    bzr_n[128 + c] = BB(2, 0) + BB(3, 0);
    bzr_u[c]       = BB(0, 1) + BB(1, 1);
    bzr_u[128 + c] = BB(2, 1) + BB(3, 1);
    bc_n[c] = BB(4, 0) + BB(5, 0);
    bc_u[c] = BB(4, 1) + BB(5, 1);
#undef BB
}

// ---------------- HMMA GEMM (fp16 2-term, 3-stage cp.async) ----------------
struct GP {
    const char* hi[4];
    const char* lo[4];
    const char* B;
    const float* bias;
    const float* H;
    const float* Z;
    float* out0;
    char* outHR;
    long Mb;
    int M, N, nparts, mode;   // mode 0=zr, 2=ch(fused cx|ch)
};

__device__ __forceinline__ void epi_pair(const GP& g, int row, int c, float v0, float v1) {
    v0 += g.bias[c];
    v1 += g.bias[c + 1];
    long rb = (long)row * D;
    if (g.mode == 0) {
        if (c < 128) {
            g.out0[rb + c] = sigf(v0);
            g.out0[rb + c + 1] = sigf(v1);
        } else {
            int cc = c - 128;
            float r0 = sigf(v0) * g.H[rb + cc];
            float r1 = sigf(v1) * g.H[rb + cc + 1];
            uint32_t hw, lw;
            split2(r0, r1, hw, lw);
            uint32_t sw = SWZ((uint32_t)row * 128u + (uint32_t)(cc & 63) * 2u);
            int q = cc >> 6;
            *(uint32_t*)(g.outHR + (long)q * g.Mb + sw) = hw;
            *(uint32_t*)(g.outHR + 2 * g.Mb + (long)q * g.Mb + sw) = lw;
        }
    } else {
        float z0 = g.Z[rb + c], z1 = g.Z[rb + c + 1];
        float h0 = g.H[rb + c], h1 = g.H[rb + c + 1];
        float t0 = tanhf(v0);
        float t1 = tanhf(v1);
        g.out0[rb + c] = z0 * h0 + (1.f - z0) * t0;
        g.out0[rb + c + 1] = z1 * h1 + (1.f - z1) * t1;
    }
}

__global__ void __launch_bounds__(256) gemm_mma(GP g) {
    extern __shared__ char smem[];
    uint32_t sb = s2u(smem);
    int tid = threadIdx.x;
    int lane = tid & 31, wid = tid >> 5;
    int wm = wid & 3, wn = wid >> 2;
    int row0 = blockIdx.x * 128;
    int col0 = blockIdx.y * 128;
    long Nb = (long)g.N * 128;
    int C = g.nparts * 4;

    float acc[2][8][4];
#pragma unroll
    for (int i = 0; i < 2; i++)
#pragma unroll
        for (int j = 0; j < 8; j++)
#pragma unroll
            for (int k = 0; k < 4; k++) acc[i][j][k] = 0.f;

    auto issue = [&](int t) {
        int buf = t % 3;
        int p = t >> 2, r = t & 3, term = r >> 1, q = r & 1;
        const char* Asrc = (term ? g.lo[p] : g.hi[p]) + (long)q * g.Mb + (long)row0 * 128;
        const char* Bsrc = g.B + (size_t)(p * 2 + q) * Nb + (long)col0 * 128;
        uint32_t Ad = sb + (uint32_t)buf * 32768u;
        uint32_t Bd = Ad + 16384u;
#pragma unroll
        for (int j = 0; j < 4; j++) {
            int idx = tid + j * 256;
            uint32_t sz = (row0 + (idx >> 3) < g.M) ? 16u : 0u;
            asm volatile("cp.async.cg.shared.global [%0], [%1], 16, %2;"
                         :: "r"(Ad + idx * 16), "l"(Asrc + (long)idx * 16), "r"(sz));
        }
#pragma unroll
        for (int j = 0; j < 4; j++) {
            int idx = tid + j * 256;
            asm volatile("cp.async.cg.shared.global [%0], [%1], 16;"
                         :: "r"(Bd + idx * 16), "l"(Bsrc + (long)idx * 16));
        }
        asm volatile("cp.async.commit_group;" ::: "memory");
    };

    issue(0);
    issue(1);
    issue(2);

    for (int t = 0; t < C; t++) {
        int rem = C - t;
        if (rem > 2)       asm volatile("cp.async.wait_group 2;" ::: "memory");
        else if (rem == 2) asm volatile("cp.async.wait_group 1;" ::: "memory");
        else               asm volatile("cp.async.wait_group 0;" ::: "memory");
        __syncthreads();
        uint32_t Ab = sb + (uint32_t)(t % 3) * 32768u;
        uint32_t Bb = Ab + 16384u;
#pragma unroll
        for (int kk = 0; kk < 4; kk++) {
            uint32_t a[2][4];
#pragma unroll
            for (int mi = 0; mi < 2; mi++) {
                int rr = wm * 32 + mi * 16 + (lane & 15);
                int byt = kk * 32 + ((lane >> 4) << 4);
                uint32_t ad = Ab + SWZ((uint32_t)(rr * 128 + byt));
                asm volatile("ldmatrix.sync.aligned.m8n8.x4.shared.b16 {%0,%1,%2,%3}, [%4];"
                    : "=r"(a[mi][0]), "=r"(a[mi][1]), "=r"(a[mi][2]), "=r"(a[mi][3])
                    : "r"(ad));
            }
            uint32_t b[8][2];
#pragma unroll
            for (int nj = 0; nj < 4; nj++) {
                int nn = wn * 64 + nj * 16 + ((lane >> 4) << 3) + (lane & 7);
                int byt = kk * 32 + (((lane >> 3) & 1) << 4);
                uint32_t bd2 = Bb + SWZ((uint32_t)(nn * 128 + byt));
                asm volatile("ldmatrix.sync.aligned.m8n8.x4.shared.b16 {%0,%1,%2,%3}, [%4];"
                    : "=r"(b[nj * 2][0]), "=r"(b[nj * 2][1]),
                      "=r"(b[nj * 2 + 1][0]), "=r"(b[nj * 2 + 1][1])
                    : "r"(bd2));
            }
#pragma unroll
            for (int mi = 0; mi < 2; mi++)
#pragma unroll
                for (int ni = 0; ni < 8; ni++) {
                    asm volatile(
                        "mma.sync.aligned.m16n8k16.row.col.f32.f16.f16.f32 "
                        "{%0,%1,%2,%3}, {%4,%5,%6,%7}, {%8,%9}, {%0,%1,%2,%3};"
                        : "+f"(acc[mi][ni][0]), "+f"(acc[mi][ni][1]),
                          "+f"(acc[mi][ni][2]), "+f"(acc[mi][ni][3])
                        : "r"(a[mi][0]), "r"(a[mi][1]), "r"(a[mi][2]), "r"(a[mi][3]),
                          "r"(b[ni][0]), "r"(b[ni][1]));
                }
        }
        __syncthreads();
        if (t + 3 < C) issue(t + 3);
    }

    int lr = lane >> 2, lc = (lane & 3) * 2;
#pragma unroll
    for (int mi = 0; mi < 2; mi++)
#pragma unroll
        for (int half = 0; half < 2; half++) {
            int row = row0 + wm * 32 + mi * 16 + half * 8 + lr;
            if (row < g.M) {
#pragma unroll
                for (int ni = 0; ni < 8; ni++) {
                    int c = col0 + wn * 64 + ni * 8 + lc;
                    epi_pair(g, row, c, acc[mi][ni][half * 2], acc[mi][ni][half * 2 + 1]);
                }
            }
        }
}

// ---------------------------------------------------------------------------
extern "C" void kernel_launch(void* const* d_in, const int* in_sizes, int n_in,
                              void* d_out, int out_size) {
    const float* x_user = (const float*)d_in[0];
    const float* x_news = (const float*)d_in[1];
    const float* h_user = (const float*)d_in[2];
    const float* h_news = (const float*)d_in[3];
    const float* Wl     = (const float*)d_in[4];
    const float* Wr     = (const float*)d_in[5];
    const float* bb     = (const float*)d_in[6];
    const int* src_un   = (const int*)d_in[7];
    const int* dst_un   = (const int*)d_in[8];
    const int* src_nu   = (const int*)d_in[9];
    const int* dst_nu   = (const int*)d_in[10];

    int NU = in_sizes[0] / D;
    int NN = in_sizes[1] / D;
    int E1 = in_sizes[7];
    int E2 = in_sizes[9];

    float* base = nullptr;
    int* deg = nullptr;
    int* idx = nullptr;
    cudaGetSymbolAddress((void**)&base, g_buf);
    cudaGetSymbolAddress((void**)&deg, g_deg);
    cudaGetSymbolAddress((void**)&idx, g_idx);

    float* Zn = base + 6 * SZF;
    float* Zu = base + 7 * SZF;
    // packed: 0 PXU, 1 PXN, 2 PHU, 3 PHN, 4 PAXN, 5 PAHN, 6 PAXU, 7 PAHU,
    //         8 PACN, 9 PACU, 10 PHRN, 11 PHRU
    auto packP = [&](int i) -> char* { return (char*)(base + (10L + i) * SZF); };

    float* wf = base + 22 * SZF;
    char* WzrN = (char*)(wf);
    char* WzrU = (char*)(wf + 131072);
    char* WcN  = (char*)(wf + 262144);
    char* WcU  = (char*)(wf + 262144 + 32768);
    float* bzr_n = wf + 262144 + 4 * 32768;
    float* bzr_u = bzr_n + 256;
    float* bc_n  = bzr_u + 256;
    float* bc_u  = bc_n + 128;

    int* deg_n = deg;
    int* deg_u = deg + MAXN;
    int* ssrc1 = idx;                      // E1 sorted-by-dst source ids
    int* ssrc2 = idx + MAXE;               // E2
    int* off_n = idx + 2 * MAXE;           // NN+1
    int* off_u = off_n + (MAXN + 8);       // NU+1
    int* cur_n = off_u + (MAXN + 8);
    int* cur_u = cur_n + MAXN;

    float* out_u = (float*)d_out;
    float* out_n = (float*)d_out + (long)NU * D;

    long MbU = (long)NU * 128, MbN = (long)NN * 128;

    cudaFuncSetAttribute(gemm_mma, cudaFuncAttributeMaxDynamicSharedMemorySize, 98304);

    cudaStream_t s1;
    cudaStreamCreateWithFlags(&s1, cudaStreamNonBlocking);
    cudaEvent_t evFork, evZero, evPacks, evSortE1, evSortE2, evZrN, evHRu, evJoin;
    cudaEventCreateWithFlags(&evFork, cudaEventDisableTiming);
    cudaEventCreateWithFlags(&evZero, cudaEventDisableTiming);
    cudaEventCreateWithFlags(&evPacks, cudaEventDisableTiming);
    cudaEventCreateWithFlags(&evSortE1, cudaEventDisableTiming);
    cudaEventCreateWithFlags(&evSortE2, cudaEventDisableTiming);
    cudaEventCreateWithFlags(&evZrN, cudaEventDisableTiming);
    cudaEventCreateWithFlags(&evHRu, cudaEventDisableTiming);
    cudaEventCreateWithFlags(&evJoin, cudaEventDisableTiming);

    // ===== capture fork =====
    cudaEventRecord(evFork, 0);
    cudaStreamWaitEvent(s1, evFork, 0);

    // ===== S0: sort E1 by dst, gather news aggregates =====
    zero_int<<<(2 * MAXN + 255) / 256, 256>>>(deg, 2 * MAXN);
    cudaEventRecord(evZero, 0);
    count_deg<<<(E1 + 255) / 256, 256>>>(dst_un, E1, deg_n);
    scan_kernel<<<1, 1024>>>(deg_n, NN, off_n, cur_n);
    scatter_kernel<<<(E1 + 255) / 256, 256>>>(src_un, dst_un, E1, cur_n, ssrc1);
    cudaEventRecord(evSortE1, 0);
    gather2_pack<<<(NN * 32 + 255) / 256, 256>>>(x_user, h_user, off_n, ssrc1, NN,
                                                 packP(4), packP(5), MbN);

    // ===== S1: all weight/input packs (overlaps S0 sort+gather) =====
    pack_w_zr<<<512, 256, 0, s1>>>(Wl, Wr, WzrN, 0);
    pack_w_zr<<<512, 256, 0, s1>>>(Wl, Wr, WzrU, 1);
    pack_w2<<<128, 256, 0, s1>>>(Wl, Wr, WcN, 4, 0, 0);
    pack_w2<<<128, 256, 0, s1>>>(Wl, Wr, WcN, 5, 0, 2);
    pack_w2<<<128, 256, 0, s1>>>(Wl, Wr, WcU, 4, 1, 0);
    pack_w2<<<128, 256, 0, s1>>>(Wl, Wr, WcU, 5, 1, 2);
    build_bias<<<1, 128, 0, s1>>>(bb, bzr_n, bzr_u, bc_n, bc_u);
    pack_kernel<<<(NU * 32 + 255) / 256, 256, 0, s1>>>(x_user, NU, packP(0));
    pack_kernel<<<(NN * 32 + 255) / 256, 256, 0, s1>>>(x_news, NN, packP(1));
    pack_kernel<<<(NU * 32 + 255) / 256, 256, 0, s1>>>(h_user, NU, packP(2));
    pack_kernel<<<(NN * 32 + 255) / 256, 256, 0, s1>>>(h_news, NN, packP(3));
    cudaEventRecord(evPacks, s1);

    // ===== S1: sort E2, gather user aggregates, zr user GEMM =====
    cudaStreamWaitEvent(s1, evZero, 0);
    count_deg<<<(E2 + 255) / 256, 256, 0, s1>>>(dst_nu, E2, deg_u);
    scan_kernel<<<1, 1024, 0, s1>>>(deg_u, NU, off_u, cur_u);
    scatter_kernel<<<(E2 + 255) / 256, 256, 0, s1>>>(src_nu, dst_nu, E2, cur_u, ssrc2);
    cudaEventRecord(evSortE2, s1);
    gather2_pack<<<(NU * 32 + 255) / 256, 256, 0, s1>>>(x_news, h_news, off_u, ssrc2, NU,
                                                        packP(6), packP(7), MbU);
    {
        GP g{};
        g.hi[0] = packP(6); g.hi[1] = packP(0); g.hi[2] = packP(7); g.hi[3] = packP(2);
        for (int p = 0; p < 4; p++) g.lo[p] = g.hi[p] + 2 * MbU;
        g.B = WzrU; g.bias = bzr_u; g.H = h_user; g.out0 = Zu; g.outHR = packP(11);
        g.Mb = MbU; g.M = NU; g.N = 256; g.nparts = 4; g.mode = 0;
        gemm_mma<<<dim3((NU + 127) / 128, 2), 256, 98304, s1>>>(g);
    }
    cudaEventRecord(evHRu, s1);

    // ===== S0: zr news GEMM (needs packs), then gather1 user =====
    cudaStreamWaitEvent(0, evPacks, 0);
    {
        GP g{};
        g.hi[0] = packP(4); g.hi[1] = packP(1); g.hi[2] = packP(5); g.hi[3] = packP(3);
        for (int p = 0; p < 4; p++) g.lo[p] = g.hi[p] + 2 * MbN;
        g.B = WzrN; g.bias = bzr_n; g.H = h_news; g.out0 = Zn; g.outHR = packP(10);
        g.Mb = MbN; g.M = NN; g.N = 256; g.nparts = 4; g.mode = 0;
        gemm_mma<<<dim3((NN + 127) / 128, 2), 256, 98304>>>(g);
    }
    cudaEventRecord(evZrN, 0);
    cudaStreamWaitEvent(0, evSortE2, 0);
    gather1_pack<<<(NU * 32 + 255) / 256, 256>>>(packP(10), MbN, off_u, ssrc2, NU,
                                                 packP(9), MbU);
    // chU on S0 (needs PHRU/Zu/PAXU/PXU from S1)
    cudaStreamWaitEvent(0, evHRu, 0);
    {
        GP g{};
        g.hi[0] = packP(6); g.hi[1] = packP(0); g.hi[2] = packP(9); g.hi[3] = packP(11);
        for (int p = 0; p < 4; p++) g.lo[p] = g.hi[p] + 2 * MbU;
        g.B = WcU; g.bias = bc_u; g.H = h_user; g.Z = Zu; g.out0 = out_u;
        g.Mb = MbU; g.M = NU; g.N = 128; g.nparts = 4; g.mode = 2;
        gemm_mma<<<dim3((NU + 127) / 128, 1), 256, 98304>>>(g);
    }

    // ===== S1: gather1 news (needs PHRU local + sortE1), then ch news =====
    cudaStreamWaitEvent(s1, evSortE1, 0);
    gather1_pack<<<(NN * 32 + 255) / 256, 256, 0, s1>>>(packP(11), MbU, off_n, ssrc1, NN,
                                                        packP(8), MbN);
    cudaStreamWaitEvent(s1, evZrN, 0);   // Zn + PHRN + PAXN from S0
    {
        GP g{};
        g.hi[0] = packP(4); g.hi[1] = packP(1); g.hi[2] = packP(8); g.hi[3] = packP(10);
        for (int p = 0; p < 4; p++) g.lo[p] = g.hi[p] + 2 * MbN;
        g.B = WcN; g.bias = bc_n; g.H = h_news; g.Z = Zn; g.out0 = out_n;
        g.Mb = MbN; g.M = NN; g.N = 128; g.nparts = 4; g.mode = 2;
        gemm_mma<<<dim3((NN + 127) / 128, 1), 256, 98304, s1>>>(g);
    }
    cudaEventRecord(evJoin, s1);

    // ===== join =====
    cudaStreamWaitEvent(0, evJoin, 0);
}

// round 10
// speedup vs baseline: 4.2956x; 1.2767x over previous
#include <cuda_runtime.h>
#include <cuda_fp16.h>
#include <math.h>
#include <stdint.h>

#define D 128
#define MAXN 50000
#define MAXE 1000000
#define SZF (50000L * 128L)

__device__ float g_buf[22L * SZF + 2 * 131072 + 4 * 32768 + 1024];
__device__ int g_deg[2 * MAXN];
__device__ int g_idx[2 * MAXE + 2 * (MAXN + 8) + 2 * MAXN];

// ---------------- helpers ----------------
__device__ __forceinline__ uint32_t s2u(const void* p) {
    uint32_t a;
    asm("{ .reg .u64 t; cvta.to.shared.u64 t, %1; cvt.u32.u64 %0, t; }" : "=r"(a) : "l"(p));
    return a;
}
__device__ __host__ __forceinline__ uint32_t SWZ(uint32_t x) { return x ^ ((x >> 3) & 0x70); }

__device__ __forceinline__ float sigf(float x) { return 1.f / (1.f + expf(-x)); }

__device__ __forceinline__ uint2 pack4_hi(float4 v) {
    __half2 a = __floats2half2_rn(v.x, v.y);
    __half2 b = __floats2half2_rn(v.z, v.w);
    uint2 r;
    r.x = *reinterpret_cast<uint32_t*>(&a);
    r.y = *reinterpret_cast<uint32_t*>(&b);
    return r;
}

// ---------------- sort-by-destination ----------------
__global__ void zero_int(int* p, int n) {
    int i = blockIdx.x * blockDim.x + threadIdx.x;
    if (i < n) p[i] = 0;
}

__global__ void count_deg(const int* __restrict__ dst, int E, int* __restrict__ deg) {
    int i = blockIdx.x * blockDim.x + threadIdx.x;
    if (i < E) atomicAdd(&deg[dst[i]], 1);
}

__global__ void scan_kernel(const int* __restrict__ deg, int n,
                            int* __restrict__ off, int* __restrict__ cur) {
    __shared__ int wsum[32];
    __shared__ int carry;
    int tid = threadIdx.x, lane = tid & 31, w = tid >> 5;
    if (tid == 0) { carry = 0; off[0] = 0; }
    __syncthreads();
    for (int base = 0; base < n; base += 1024) {
        int i = base + tid;
        int v = (i < n) ? deg[i] : 0;
        int x = v;
#pragma unroll
        for (int o = 1; o < 32; o <<= 1) {
            int y = __shfl_up_sync(0xFFFFFFFFu, x, o);
            if (lane >= o) x += y;
        }
        if (lane == 31) wsum[w] = x;
        __syncthreads();
        if (w == 0) {
            int s = wsum[lane];
#pragma unroll
            for (int o = 1; o < 32; o <<= 1) {
                int y = __shfl_up_sync(0xFFFFFFFFu, s, o);
                if (lane >= o) s += y;
            }
            wsum[lane] = s;
        }
        __syncthreads();
        int incl = x + (w ? wsum[w - 1] : 0) + carry;
        if (i < n) { off[i + 1] = incl; cur[i] = incl - v; }
        __syncthreads();
        if (tid == 1023) carry = incl;
        __syncthreads();
    }
}

__global__ void scatter_kernel(const int* __restrict__ src, const int* __restrict__ dst,
                               int E, int* __restrict__ cur, int* __restrict__ ssrc) {
    int i = blockIdx.x * blockDim.x + threadIdx.x;
    if (i < E) {
        int pos = atomicAdd(&cur[dst[i]], 1);
        ssrc[pos] = src[i];
    }
}

// ---------------- packing ----------------
// fp32 [M,128] -> fp16 SW128 chunks (hi only)
__global__ void pack_hi(const float* __restrict__ src, int M, char* __restrict__ dst) {
    long i = blockIdx.x * (long)blockDim.x + threadIdx.x;
    if (i >= (long)M * 32) return;
    int row = (int)(i >> 5);
    int c4 = ((int)i & 31) * 4;
    float4 v = ((const float4*)src)[i];
    uint2 hu = pack4_hi(v);
    int q = c4 >> 6;
    int inner = c4 & 63;
    uint32_t sw = SWZ((uint32_t)row * 128u + (uint32_t)inner * 2u);
    long Mb = (long)M * 128;
    *(uint2*)(dst + (long)q * Mb + sw) = hu;
}

// pull aggregation from packed fp16 tables (x and h), warp-per-node, no atomics
__global__ void gather2_p(const char* __restrict__ Px, const char* __restrict__ Ph, long MbS,
                          const int* __restrict__ off, const int* __restrict__ ssrc, int n,
                          char* __restrict__ Ox, char* __restrict__ Oh, long MbD) {
    long gid = blockIdx.x * (long)blockDim.x + threadIdx.x;
    int node = (int)(gid >> 5), lane = (int)(gid & 31);
    if (node >= n) return;
    int s0 = off[node], s1 = off[node + 1];
    int c4 = lane * 4;
    int q = c4 >> 6;
    int inner = c4 & 63;
    float4 sx = make_float4(0.f, 0.f, 0.f, 0.f);
    float4 sh = make_float4(0.f, 0.f, 0.f, 0.f);
    int i = s0;
    for (; i + 1 < s1; i += 2) {
        int a = ssrc[i], b = ssrc[i + 1];
        uint32_t swa = SWZ((uint32_t)a * 128u + (uint32_t)inner * 2u);
        uint32_t swb = SWZ((uint32_t)b * 128u + (uint32_t)inner * 2u);
        uint2 xa = *(const uint2*)(Px + (long)q * MbS + swa);
        uint2 xb = *(const uint2*)(Px + (long)q * MbS + swb);
        uint2 ha = *(const uint2*)(Ph + (long)q * MbS + swa);
        uint2 hb = *(const uint2*)(Ph + (long)q * MbS + swb);
        float2 p0 = __half22float2(*reinterpret_cast<__half2*>(&xa.x));
        float2 p1 = __half22float2(*reinterpret_cast<__half2*>(&xa.y));
        float2 p2 = __half22float2(*reinterpret_cast<__half2*>(&xb.x));
        float2 p3 = __half22float2(*reinterpret_cast<__half2*>(&xb.y));
        sx.x += p0.x + p2.x; sx.y += p0.y + p2.y; sx.z += p1.x + p3.x; sx.w += p1.y + p3.y;
        p0 = __half22float2(*reinterpret_cast<__half2*>(&ha.x));
        p1 = __half22float2(*reinterpret_cast<__half2*>(&ha.y));
        p2 = __half22float2(*reinterpret_cast<__half2*>(&hb.x));
        p3 = __half22float2(*reinterpret_cast<__half2*>(&hb.y));
        sh.x += p0.x + p2.x; sh.y += p0.y + p2.y; sh.z += p1.x + p3.x; sh.w += p1.y + p3.y;
    }
    if (i < s1) {
        int a = ssrc[i];
        uint32_t swa = SWZ((uint32_t)a * 128u + (uint32_t)inner * 2u);
        uint2 xa = *(const uint2*)(Px + (long)q * MbS + swa);
        uint2 ha = *(const uint2*)(Ph + (long)q * MbS + swa);
        float2 p0 = __half22float2(*reinterpret_cast<__half2*>(&xa.x));
        float2 p1 = __half22float2(*reinterpret_cast<__half2*>(&xa.y));
        sx.x += p0.x; sx.y += p0.y; sx.z += p1.x; sx.w += p1.y;
        p0 = __half22float2(*reinterpret_cast<__half2*>(&ha.x));
        p1 = __half22float2(*reinterpret_cast<__half2*>(&ha.y));
        sh.x += p0.x; sh.y += p0.y; sh.z += p1.x; sh.w += p1.y;
    }
    float inv = 1.f / (float)max(s1 - s0, 1);
    sx.x *= inv; sx.y *= inv; sx.z *= inv; sx.w *= inv;
    sh.x *= inv; sh.y *= inv; sh.z *= inv; sh.w *= inv;
    uint32_t swd = SWZ((uint32_t)node * 128u + (uint32_t)inner * 2u);
    *(uint2*)(Ox + (long)q * MbD + swd) = pack4_hi(sx);
    *(uint2*)(Oh + (long)q * MbD + swd) = pack4_hi(sh);
}

// pull aggregation of one packed table -> packed output
__global__ void gather1_p(const char* __restrict__ P, long MbS,
                          const int* __restrict__ off, const int* __restrict__ ssrc, int n,
                          char* __restrict__ dstP, long MbD) {
    long gid = blockIdx.x * (long)blockDim.x + threadIdx.x;
    int node = (int)(gid >> 5), lane = (int)(gid & 31);
    if (node >= n) return;
    int s0 = off[node], s1 = off[node + 1];
    int c4 = lane * 4;
    int q = c4 >> 6;
    int inner = c4 & 63;
    float4 acc = make_float4(0.f, 0.f, 0.f, 0.f);
    int i = s0;
    for (; i + 1 < s1; i += 2) {
        int a = ssrc[i], b = ssrc[i + 1];
        uint2 ha = *(const uint2*)(P + (long)q * MbS + SWZ((uint32_t)a * 128u + (uint32_t)inner * 2u));
        uint2 hb = *(const uint2*)(P + (long)q * MbS + SWZ((uint32_t)b * 128u + (uint32_t)inner * 2u));
        float2 p0 = __half22float2(*reinterpret_cast<__half2*>(&ha.x));
        float2 p1 = __half22float2(*reinterpret_cast<__half2*>(&ha.y));
        float2 p2 = __half22float2(*reinterpret_cast<__half2*>(&hb.x));
        float2 p3 = __half22float2(*reinterpret_cast<__half2*>(&hb.y));
        acc.x += p0.x + p2.x; acc.y += p0.y + p2.y; acc.z += p1.x + p3.x; acc.w += p1.y + p3.y;
    }
    if (i < s1) {
        int a = ssrc[i];
        uint2 ha = *(const uint2*)(P + (long)q * MbS + SWZ((uint32_t)a * 128u + (uint32_t)inner * 2u));
        float2 p0 = __half22float2(*reinterpret_cast<__half2*>(&ha.x));
        float2 p1 = __half22float2(*reinterpret_cast<__half2*>(&ha.y));
        acc.x += p0.x; acc.y += p0.y; acc.z += p1.x; acc.w += p1.y;
    }
    float inv = 1.f / (float)max(s1 - s0, 1);
    acc.x *= inv; acc.y *= inv; acc.z *= inv; acc.w *= inv;
    uint32_t swd = SWZ((uint32_t)node * 128u + (uint32_t)inner * 2u);
    *(uint2*)(dstP + (long)q * MbD + swd) = pack4_hi(acc);
}

// ---------------- weight packing (fp16) ----------------
__global__ void pack_w_zr(const float* __restrict__ Wl, const float* __restrict__ Wr,
                          char* __restrict__ dst, int t) {
    int j = blockIdx.x * blockDim.x + threadIdx.x;
    if (j >= 4 * 256 * 128) return;
    int k = j & 127;
    int n = (j >> 7) & 255;
    int p = j >> 15;
    int gz = (n < 128) ? 0 : 2;
    int cc = n & 127;
    int g = gz + (p >> 1);
    const float* S = (p & 1) ? Wr : Wl;
    float w = S[((long)(g * 2 + t) * 128 + k) * 128 + cc];
    __half h = __float2half_rn(w);
    int q = k >> 6;
    int inner = k & 63;
    uint32_t sw = SWZ((uint32_t)n * 128u + (uint32_t)inner * 2u);
    const int Nb = 256 * 128;
    *(unsigned short*)(dst + (size_t)(p * 2 + q) * Nb + sw) = *reinterpret_cast<unsigned short*>(&h);
}

__global__ void pack_w2(const float* __restrict__ Wl, const float* __restrict__ Wr,
                        char* __restrict__ dst, int g, int t, int pbase) {
    int j = blockIdx.x * blockDim.x + threadIdx.x;
    if (j >= 2 * 128 * 128) return;
    int k = j & 127;
    int n = (j >> 7) & 127;
    int p = j >> 14;
    const float* S = p ? Wr : Wl;
    float w = S[((long)(g * 2 + t) * 128 + k) * 128 + n];
    __half h = __float2half_rn(w);
    int q = k >> 6;
    int inner = k & 63;
    uint32_t sw = SWZ((uint32_t)n * 128u + (uint32_t)inner * 2u);
    const int Nb = 128 * 128;
    *(unsigned short*)(dst + (size_t)((pbase + p) * 2 + q) * Nb + sw) = *reinterpret_cast<unsigned short*>(&h);
}

__global__ void build_bias(const float* __restrict__ b,
                           float* bzr_n, float* bzr_u, float* bc_n, float* bc_u) {
    int c = threadIdx.x;
    if (c >= 128) return;
#define BB(g, t) b[((g) * 2 + (t)) * 128 + c]
    bzr_n[c]       = BB(0, 0) + BB(1, 0);
    bzr_n[128 + c] = BB(2, 0) + BB(3, 0);
    bzr_u[c]       = BB(0, 1) + BB(1, 1);
    bzr_u[128 + c] = BB(2, 1) + BB(3, 1);
    bc_n[c] = BB(4, 0) + BB(5, 0);
    bc_u[c] = BB(4, 1) + BB(5, 1);
#undef BB
}

// ---------------- HMMA GEMM (single fp16 term, 3-stage cp.async) ----------
struct GP {
    const char* hi[4];
    const char* B;
    const float* bias;
    const float* H;
    const float* Z;
    float* out0;
    char* outHR;
    long Mb;
    int M, N, nparts, mode;   // mode 0=zr, 2=ch
};

__device__ __forceinline__ void epi_pair(const GP& g, int row, int c, float v0, float v1) {
    v0 += g.bias[c];
    v1 += g.bias[c + 1];
    long rb = (long)row * D;
    if (g.mode == 0) {
        if (c < 128) {
            g.out0[rb + c] = sigf(v0);
            g.out0[rb + c + 1] = sigf(v1);
        } else {
            int cc = c - 128;
            float r0 = sigf(v0) * g.H[rb + cc];
            float r1 = sigf(v1) * g.H[rb + cc + 1];
            __half2 h = __floats2half2_rn(r0, r1);
            uint32_t sw = SWZ((uint32_t)row * 128u + (uint32_t)(cc & 63) * 2u);
            int q = cc >> 6;
            *(uint32_t*)(g.outHR + (long)q * g.Mb + sw) = *reinterpret_cast<uint32_t*>(&h);
        }
    } else {
        float z0 = g.Z[rb + c], z1 = g.Z[rb + c + 1];
        float h0 = g.H[rb + c], h1 = g.H[rb + c + 1];
        float t0 = tanhf(v0);
        float t1 = tanhf(v1);
        g.out0[rb + c] = z0 * h0 + (1.f - z0) * t0;
        g.out0[rb + c + 1] = z1 * h1 + (1.f - z1) * t1;
    }
}

__global__ void __launch_bounds__(256) gemm_mma(GP g) {
    extern __shared__ char smem[];
    uint32_t sb = s2u(smem);
    int tid = threadIdx.x;
    int lane = tid & 31, wid = tid >> 5;
    int wm = wid & 3, wn = wid >> 2;
    int row0 = blockIdx.x * 128;
    int col0 = blockIdx.y * 128;
    long Nb = (long)g.N * 128;     // weight block stride
    int C = g.nparts * 2;          // parts x 2 chunks (single term)

    float acc[2][8][4];
#pragma unroll
    for (int i = 0; i < 2; i++)
#pragma unroll
        for (int j = 0; j < 8; j++)
#pragma unroll
            for (int k = 0; k < 4; k++) acc[i][j][k] = 0.f;

    auto issue = [&](int t) {
        int buf = t % 3;
        int p = t >> 1, q = t & 1;
        const char* Asrc = g.hi[p] + (long)q * g.Mb + (long)row0 * 128;
        const char* Bsrc = g.B + (size_t)(p * 2 + q) * Nb + (long)col0 * 128;
        uint32_t Ad = sb + (uint32_t)buf * 32768u;
        uint32_t Bd = Ad + 16384u;
#pragma unroll
        for (int j = 0; j < 4; j++) {
            int idx = tid + j * 256;
            uint32_t sz = (row0 + (idx >> 3) < g.M) ? 16u : 0u;
            asm volatile("cp.async.cg.shared.global [%0], [%1], 16, %2;"
                         :: "r"(Ad + idx * 16), "l"(Asrc + (long)idx * 16), "r"(sz));
        }
        // B tile: 128 rows x 128B = 16KB (only this CTA's col slice)
#pragma unroll
        for (int j = 0; j < 4; j++) {
            int idx = tid + j * 256;
            asm volatile("cp.async.cg.shared.global [%0], [%1], 16;"
                         :: "r"(Bd + idx * 16), "l"(Bsrc + (long)idx * 16));
        }
        asm volatile("cp.async.commit_group;" ::: "memory");
    };

    issue(0);
    issue(1);
    issue(2);

    for (int t = 0; t < C; t++) {
        int rem = C - t;
        if (rem > 2)       asm volatile("cp.async.wait_group 2;" ::: "memory");
        else if (rem == 2) asm volatile("cp.async.wait_group 1;" ::: "memory");
        else               asm volatile("cp.async.wait_group 0;" ::: "memory");
        __syncthreads();
        uint32_t Ab = sb + (uint32_t)(t % 3) * 32768u;
        uint32_t Bb = Ab + 16384u;
#pragma unroll
        for (int kk = 0; kk < 4; kk++) {
            uint32_t a[2][4];
#pragma unroll
            for (int mi = 0; mi < 2; mi++) {
                int rr = wm * 32 + mi * 16 + (lane & 15);
                int byt = kk * 32 + ((lane >> 4) << 4);
                uint32_t ad = Ab + SWZ((uint32_t)(rr * 128 + byt));
                asm volatile("ldmatrix.sync.aligned.m8n8.x4.shared.b16 {%0,%1,%2,%3}, [%4];"
                    : "=r"(a[mi][0]), "=r"(a[mi][1]), "=r"(a[mi][2]), "=r"(a[mi][3])
                    : "r"(ad));
            }
            uint32_t b[8][2];
#pragma unroll
            for (int nj = 0; nj < 4; nj++) {
                int nn = wn * 64 + nj * 16 + ((lane >> 4) << 3) + (lane & 7);
                int byt = kk * 32 + (((lane >> 3) & 1) << 4);
                uint32_t bd2 = Bb + SWZ((uint32_t)(nn * 128 + byt));
                asm volatile("ldmatrix.sync.aligned.m8n8.x4.shared.b16 {%0,%1,%2,%3}, [%4];"
                    : "=r"(b[nj * 2][0]), "=r"(b[nj * 2][1]),
                      "=r"(b[nj * 2 + 1][0]), "=r"(b[nj * 2 + 1][1])
                    : "r"(bd2));
            }
#pragma unroll
            for (int mi = 0; mi < 2; mi++)
#pragma unroll
                for (int ni = 0; ni < 8; ni++) {
                    asm volatile(
                        "mma.sync.aligned.m16n8k16.row.col.f32.f16.f16.f32 "
                        "{%0,%1,%2,%3}, {%4,%5,%6,%7}, {%8,%9}, {%0,%1,%2,%3};"
                        : "+f"(acc[mi][ni][0]), "+f"(acc[mi][ni][1]),
                          "+f"(acc[mi][ni][2]), "+f"(acc[mi][ni][3])
                        : "r"(a[mi][0]), "r"(a[mi][1]), "r"(a[mi][2]), "r"(a[mi][3]),
                          "r"(b[ni][0]), "r"(b[ni][1]));
                }
        }
        __syncthreads();
        if (t + 3 < C) issue(t + 3);
    }

    int lr = lane >> 2, lc = (lane & 3) * 2;
#pragma unroll
    for (int mi = 0; mi < 2; mi++)
#pragma unroll
        for (int half = 0; half < 2; half++) {
            int row = row0 + wm * 32 + mi * 16 + half * 8 + lr;
            if (row < g.M) {
#pragma unroll
                for (int ni = 0; ni < 8; ni++) {
                    int c = col0 + wn * 64 + ni * 8 + lc;
                    epi_pair(g, row, c, acc[mi][ni][half * 2], acc[mi][ni][half * 2 + 1]);
                }
            }
        }
}

// ---------------------------------------------------------------------------
extern "C" void kernel_launch(void* const* d_in, const int* in_sizes, int n_in,
                              void* d_out, int out_size) {
    const float* x_user = (const float*)d_in[0];
    const float* x_news = (const float*)d_in[1];
    const float* h_user = (const float*)d_in[2];
    const float* h_news = (const float*)d_in[3];
    const float* Wl     = (const float*)d_in[4];
    const float* Wr     = (const float*)d_in[5];
    const float* bb     = (const float*)d_in[6];
    const int* src_un   = (const int*)d_in[7];
    const int* dst_un   = (const int*)d_in[8];
    const int* src_nu   = (const int*)d_in[9];
    const int* dst_nu   = (const int*)d_in[10];

    int NU = in_sizes[0] / D;
    int NN = in_sizes[1] / D;
    int E1 = in_sizes[7];
    int E2 = in_sizes[9];

    float* base = nullptr;
    int* deg = nullptr;
    int* idx = nullptr;
    cudaGetSymbolAddress((void**)&base, g_buf);
    cudaGetSymbolAddress((void**)&deg, g_deg);
    cudaGetSymbolAddress((void**)&idx, g_idx);

    float* Zn = base + 6 * SZF;
    float* Zu = base + 7 * SZF;
    // packed hi-only: 0 PXU, 1 PXN, 2 PHU, 3 PHN, 4 PAXN, 5 PAHN, 6 PAXU,
    //                 7 PAHU, 8 PACN, 9 PACU, 10 PHRN, 11 PHRU
    auto packP = [&](int i) -> char* { return (char*)(base + (10L + i) * SZF); };

    float* wf = base + 22 * SZF;
    char* WzrN = (char*)(wf);
    char* WzrU = (char*)(wf + 131072);
    char* WcN  = (char*)(wf + 262144);
    char* WcU  = (char*)(wf + 262144 + 32768);
    float* bzr_n = wf + 262144 + 4 * 32768;
    float* bzr_u = bzr_n + 256;
    float* bc_n  = bzr_u + 256;
    float* bc_u  = bc_n + 128;

    int* deg_n = deg;
    int* deg_u = deg + MAXN;
    int* ssrc1 = idx;
    int* ssrc2 = idx + MAXE;
    int* off_n = idx + 2 * MAXE;
    int* off_u = off_n + (MAXN + 8);
    int* cur_n = off_u + (MAXN + 8);
    int* cur_u = cur_n + MAXN;

    float* out_u = (float*)d_out;
    float* out_n = (float*)d_out + (long)NU * D;

    long MbU = (long)NU * 128, MbN = (long)NN * 128;

    cudaFuncSetAttribute(gemm_mma, cudaFuncAttributeMaxDynamicSharedMemorySize, 98304);

    cudaStream_t s1;
    cudaStreamCreateWithFlags(&s1, cudaStreamNonBlocking);
    cudaEvent_t evFork, evPackXH, evPacksW, evSortE1, evSortE2, evZrN, evHRu, evJoin;
    cudaEventCreateWithFlags(&evFork, cudaEventDisableTiming);
    cudaEventCreateWithFlags(&evPackXH, cudaEventDisableTiming);
    cudaEventCreateWithFlags(&evPacksW, cudaEventDisableTiming);
    cudaEventCreateWithFlags(&evSortE1, cudaEventDisableTiming);
    cudaEventCreateWithFlags(&evSortE2, cudaEventDisableTiming);
    cudaEventCreateWithFlags(&evZrN, cudaEventDisableTiming);
    cudaEventCreateWithFlags(&evHRu, cudaEventDisableTiming);
    cudaEventCreateWithFlags(&evJoin, cudaEventDisableTiming);

    // ===== capture fork =====
    cudaEventRecord(evFork, 0);
    cudaStreamWaitEvent(s1, evFork, 0);

    // ===== S0: sort E1 =====
    zero_int<<<(MAXN + 255) / 256, 256>>>(deg_n, MAXN);
    count_deg<<<(E1 + 255) / 256, 256>>>(dst_un, E1, deg_n);
    scan_kernel<<<1, 1024>>>(deg_n, NN, off_n, cur_n);
    scatter_kernel<<<(E1 + 255) / 256, 256>>>(src_un, dst_un, E1, cur_n, ssrc1);
    cudaEventRecord(evSortE1, 0);

    // ===== S1: input packs, weight packs =====
    pack_hi<<<(NU * 32 + 255) / 256, 256, 0, s1>>>(x_user, NU, packP(0));
    pack_hi<<<(NN * 32 + 255) / 256, 256, 0, s1>>>(x_news, NN, packP(1));
    pack_hi<<<(NU * 32 + 255) / 256, 256, 0, s1>>>(h_user, NU, packP(2));
    pack_hi<<<(NN * 32 + 255) / 256, 256, 0, s1>>>(h_news, NN, packP(3));
    cudaEventRecord(evPackXH, s1);
    pack_w_zr<<<512, 256, 0, s1>>>(Wl, Wr, WzrN, 0);
    pack_w_zr<<<512, 256, 0, s1>>>(Wl, Wr, WzrU, 1);
    pack_w2<<<128, 256, 0, s1>>>(Wl, Wr, WcN, 4, 0, 0);
    pack_w2<<<128, 256, 0, s1>>>(Wl, Wr, WcN, 5, 0, 2);
    pack_w2<<<128, 256, 0, s1>>>(Wl, Wr, WcU, 4, 1, 0);
    pack_w2<<<128, 256, 0, s1>>>(Wl, Wr, WcU, 5, 1, 2);
    build_bias<<<1, 128, 0, s1>>>(bb, bzr_n, bzr_u, bc_n, bc_u);
    cudaEventRecord(evPacksW, s1);

    // ===== S0: gather news aggregates from packed, zr news GEMM =====
    cudaStreamWaitEvent(0, evPackXH, 0);
    gather2_p<<<(NN * 32 + 255) / 256, 256>>>(packP(0), packP(2), MbU, off_n, ssrc1, NN,
                                              packP(4), packP(5), MbN);
    cudaStreamWaitEvent(0, evPacksW, 0);
    {
        GP g{};
        g.hi[0] = packP(4); g.hi[1] = packP(1); g.hi[2] = packP(5); g.hi[3] = packP(3);
        g.B = WzrN; g.bias = bzr_n; g.H = h_news; g.out0 = Zn; g.outHR = packP(10);
        g.Mb = MbN; g.M = NN; g.N = 256; g.nparts = 4; g.mode = 0;
        gemm_mma<<<dim3((NN + 127) / 128, 2), 256, 98304>>>(g);
    }
    cudaEventRecord(evZrN, 0);

    // ===== S1: sort E2, gather user aggregates, zr user GEMM =====
    zero_int<<<(MAXN + 255) / 256, 256, 0, s1>>>(deg_u, MAXN);
    count_deg<<<(E2 + 255) / 256, 256, 0, s1>>>(dst_nu, E2, deg_u);
    scan_kernel<<<1, 1024, 0, s1>>>(deg_u, NU, off_u, cur_u);
    scatter_kernel<<<(E2 + 255) / 256, 256, 0, s1>>>(src_nu, dst_nu, E2, cur_u, ssrc2);
    cudaEventRecord(evSortE2, s1);
    gather2_p<<<(NU * 32 + 255) / 256, 256, 0, s1>>>(packP(1), packP(3), MbN, off_u, ssrc2, NU,
                                                     packP(6), packP(7), MbU);
    {
        GP g{};
        g.hi[0] = packP(6); g.hi[1] = packP(0); g.hi[2] = packP(7); g.hi[3] = packP(2);
        g.B = WzrU; g.bias = bzr_u; g.H = h_user; g.out0 = Zu; g.outHR = packP(11);
        g.Mb = MbU; g.M = NU; g.N = 256; g.nparts = 4; g.mode = 0;
        gemm_mma<<<dim3((NU + 127) / 128, 2), 256, 98304, s1>>>(g);
    }
    cudaEventRecord(evHRu, s1);

    // ===== S0: gather1 E2 (PHRN -> PACU), chU GEMM -> out_u =====
    cudaStreamWaitEvent(0, evSortE2, 0);
    gather1_p<<<(NU * 32 + 255) / 256, 256>>>(packP(10), MbN, off_u, ssrc2, NU,
                                              packP(9), MbU);
    cudaStreamWaitEvent(0, evHRu, 0);
    {
        GP g{};
        g.hi[0] = packP(6); g.hi[1] = packP(0); g.hi[2] = packP(9); g.hi[3] = packP(11);
        g.B = WcU; g.bias = bc_u; g.H = h_user; g.Z = Zu; g.out0 = out_u;
        g.Mb = MbU; g.M = NU; g.N = 128; g.nparts = 4; g.mode = 2;
        gemm_mma<<<dim3((NU + 127) / 128, 1), 256, 98304>>>(g);
    }

    // ===== S1: gather1 E1 (PHRU -> PACN), chN GEMM -> out_n =====
    cudaStreamWaitEvent(s1, evSortE1, 0);
    gather1_p<<<(NN * 32 + 255) / 256, 256, 0, s1>>>(packP(11), MbU, off_n, ssrc1, NN,
                                                     packP(8), MbN);
    cudaStreamWaitEvent(s1, evZrN, 0);
    {
        GP g{};
        g.hi[0] = packP(4); g.hi[1] = packP(1); g.hi[2] = packP(8); g.hi[3] = packP(10);
        g.B = WcN; g.bias = bc_n; g.H = h_news; g.Z = Zn; g.out0 = out_n;
        g.Mb = MbN; g.M = NN; g.N = 128; g.nparts = 4; g.mode = 2;
        gemm_mma<<<dim3((NN + 127) / 128, 1), 256, 98304, s1>>>(g);
    }
    cudaEventRecord(evJoin, s1);

    // ===== join =====
    cudaStreamWaitEvent(0, evJoin, 0);
}